// round 4
// baseline (speedup 1.0000x reference)
#include <cuda_runtime.h>
#include <math.h>

#define TT   512
#define BB   64
#define DD   1024
#define AA   128
#define AIN  2176            // D + D + A
#define KTOT 2304            // AIN + A (whh folded into composite K)
#define PSZ  14336           // 14*D
#define NL   2
#define NCTA 128
#define NTHR 256

// ---------------- persistent state ----------------------------------------
__device__ float s_ah[2][NL][BB * AA];   // [parity][layer][m*A + j]
__device__ float s_ahT[AA * BB];         // transposed ah_new of current layer
__device__ float s_ac[NL][BB * AA];
__device__ float s_fh[2][NL][BB * DD];
__device__ float s_fc[NL][BB * DD];
__device__ float s_pol[(size_t)BB * PSZ];

// ---------------- software grid barrier ------------------------------------
__device__ unsigned g_cnt = 0;
__device__ volatile unsigned g_gen = 0;

__device__ __forceinline__ void grid_sync() {
    __threadfence();                 // release this thread's global writes
    __syncthreads();
    if (threadIdx.x == 0) {
        unsigned gen = g_gen;
        if (atomicAdd(&g_cnt, 1u) == NCTA - 1) {
            g_cnt = 0;
            __threadfence();
            g_gen = gen + 1;
        } else {
            while (g_gen == gen) { __nanosleep(64); }
        }
        __threadfence();             // gpu-scope fence -> L1D invalidate
    }
    __syncthreads();
}

__device__ __forceinline__ float sigf(float x) { return 1.0f / (1.0f + expf(-x)); }

struct Params {
    const float* x;
    const float* awih[2]; const float* awhh[2];
    const float* abih[2]; const float* abhh[2];
    const float* pw[2];   const float* pb[2];
    const float* fwih[2]; const float* fwhh[2]; const float* fb[2];
    float* out;
};

// ---------------- stage 1: attention-LSTM ----------------------------------
// CTA b handles hidden col j=b (4 gate cols). thread = (m = tid>>2, c = tid&3).
// Composite K = 2304: [xc | fh_old | ah_other | ah_self].
__device__ __forceinline__ void stage1(
    int l, int p, const float* __restrict__ xt,
    const float* __restrict__ awih, const float* __restrict__ awhh,
    const float* __restrict__ abih, const float* __restrict__ abhh,
    float* sm)
{
    float* a_sm = sm;            // [m*68 + kk], 64 x 68
    float* w_sm = sm + 4352;     // [c*68 + kk],  4 x 68
    const int tid = threadIdx.x;
    const int j   = blockIdx.x;
    const int m   = tid >> 2;
    const int c   = tid & 3;

    const float* xc      = (l == 0) ? xt : s_fh[p ^ 1][0];
    const float* fhOld   = s_fh[p][l];
    const float* ahSelf  = s_ah[p][l];
    const float* ahOther = (l == 0) ? s_ah[p][1] : s_ah[p ^ 1][0];

    float acc0 = 0.f, acc1 = 0.f;

    for (int k0 = 0; k0 < KTOT; k0 += 64) {
        {   // weights: 4 gate-cols x 64 k, one element per thread
            int cc = tid >> 6, kk = tid & 63, k = k0 + kk;
            int n = cc * AA + j;
            w_sm[cc * 68 + kk] = (k < AIN) ? awih[(size_t)n * AIN + k]
                                           : awhh[n * AA + (k - AIN)];
        }
        #pragma unroll
        for (int r = 0; r < 16; r++) {       // activations: 64m x 64k
            int i = r * 256 + tid;
            int mi = i >> 6, kk = i & 63, k = k0 + kk;
            float v;
            if (k < DD)            v = xc[mi * DD + k];
            else if (k < 2 * DD)   v = fhOld[mi * DD + (k - DD)];
            else if (k < AIN)      v = ahOther[mi * AA + (k - 2 * DD)];
            else                   v = ahSelf[mi * AA + (k - AIN)];
            a_sm[mi * 68 + kk] = v;
        }
        __syncthreads();
        const float4* av = (const float4*)(a_sm + m * 68);
        const float4* wv = (const float4*)(w_sm + c * 68);
        #pragma unroll
        for (int q = 0; q < 16; q++) {
            float4 a4 = av[q], w4 = wv[q];
            acc0 = fmaf(a4.x, w4.x, acc0);
            acc1 = fmaf(a4.y, w4.y, acc1);
            acc0 = fmaf(a4.z, w4.z, acc0);
            acc1 = fmaf(a4.w, w4.w, acc1);
        }
        __syncthreads();
    }

    float g = acc0 + acc1 + abih[c * AA + j] + abhh[c * AA + j];
    const unsigned FULL = 0xffffffffu;
    int base = (tid & 31) & ~3;
    float gi = __shfl_sync(FULL, g, base + 0);
    float gf = __shfl_sync(FULL, g, base + 1);
    float gz = __shfl_sync(FULL, g, base + 2);
    float go = __shfl_sync(FULL, g, base + 3);
    if (c == 0) {
        float cO = s_ac[l][m * AA + j];
        float cN = sigf(gf) * cO + sigf(gi) * tanhf(gz);
        float h  = sigf(go) * tanhf(cN);
        s_ac[l][m * AA + j] = cN;
        s_ah[p ^ 1][l][m * AA + j] = h;
        s_ahT[j * BB + m] = h;           // transposed copy for stage2
    }
}

// ---------------- stage 2: pol = ah_new @ pw.T + pb ------------------------
// CTAs 0..111, Ntile=128, thread tile 4m x 8n, K=128 in 4 chunks of 32.
__device__ __forceinline__ void stage2(
    int l, int p, const float* __restrict__ pw, const float* __restrict__ pb,
    float* sm)
{
    const int b = blockIdx.x;
    if (b >= 112) return;
    float* a_sm = sm;            // [kk*68 + m],  32 x 68
    float* w_sm = sm + 2176;     // [kk*132 + nn], 32 x 132
    const int tid = threadIdx.x;
    const int n0  = b * 128;
    const int mg  = tid & 15;
    const int ng  = tid >> 4;

    float acc[4][8];
    #pragma unroll
    for (int r = 0; r < 4; r++)
        #pragma unroll
        for (int q = 0; q < 8; q++) acc[r][q] = 0.f;

    for (int kc = 0; kc < AA; kc += 32) {
        #pragma unroll
        for (int r = 0; r < 8; r++) {        // a: 32k x 64m (from ahT: coalesced)
            int i = r * 256 + tid;
            int kk = i >> 6, mi = i & 63;
            a_sm[kk * 68 + mi] = s_ahT[(kc + kk) * BB + mi];
        }
        #pragma unroll
        for (int r = 0; r < 16; r++) {       // w: 128n x 32k
            int i = r * 256 + tid;
            int nn = i >> 5, kk = i & 31;
            w_sm[kk * 132 + nn] = pw[(size_t)(n0 + nn) * AA + kc + kk];
        }
        __syncthreads();
        #pragma unroll
        for (int kk = 0; kk < 32; kk++) {
            float4 a4 = *(const float4*)(a_sm + kk * 68 + 4 * mg);
            float4 wA = *(const float4*)(w_sm + kk * 132 + 8 * ng);
            float4 wB = *(const float4*)(w_sm + kk * 132 + 8 * ng + 4);
            acc[0][0] = fmaf(a4.x, wA.x, acc[0][0]);
            acc[0][1] = fmaf(a4.x, wA.y, acc[0][1]);
            acc[0][2] = fmaf(a4.x, wA.z, acc[0][2]);
            acc[0][3] = fmaf(a4.x, wA.w, acc[0][3]);
            acc[0][4] = fmaf(a4.x, wB.x, acc[0][4]);
            acc[0][5] = fmaf(a4.x, wB.y, acc[0][5]);
            acc[0][6] = fmaf(a4.x, wB.z, acc[0][6]);
            acc[0][7] = fmaf(a4.x, wB.w, acc[0][7]);
            acc[1][0] = fmaf(a4.y, wA.x, acc[1][0]);
            acc[1][1] = fmaf(a4.y, wA.y, acc[1][1]);
            acc[1][2] = fmaf(a4.y, wA.z, acc[1][2]);
            acc[1][3] = fmaf(a4.y, wA.w, acc[1][3]);
            acc[1][4] = fmaf(a4.y, wB.x, acc[1][4]);
            acc[1][5] = fmaf(a4.y, wB.y, acc[1][5]);
            acc[1][6] = fmaf(a4.y, wB.z, acc[1][6]);
            acc[1][7] = fmaf(a4.y, wB.w, acc[1][7]);
            acc[2][0] = fmaf(a4.z, wA.x, acc[2][0]);
            acc[2][1] = fmaf(a4.z, wA.y, acc[2][1]);
            acc[2][2] = fmaf(a4.z, wA.z, acc[2][2]);
            acc[2][3] = fmaf(a4.z, wA.w, acc[2][3]);
            acc[2][4] = fmaf(a4.z, wB.x, acc[2][4]);
            acc[2][5] = fmaf(a4.z, wB.y, acc[2][5]);
            acc[2][6] = fmaf(a4.z, wB.z, acc[2][6]);
            acc[2][7] = fmaf(a4.z, wB.w, acc[2][7]);
            acc[3][0] = fmaf(a4.w, wA.x, acc[3][0]);
            acc[3][1] = fmaf(a4.w, wA.y, acc[3][1]);
            acc[3][2] = fmaf(a4.w, wA.z, acc[3][2]);
            acc[3][3] = fmaf(a4.w, wA.w, acc[3][3]);
            acc[3][4] = fmaf(a4.w, wB.x, acc[3][4]);
            acc[3][5] = fmaf(a4.w, wB.y, acc[3][5]);
            acc[3][6] = fmaf(a4.w, wB.z, acc[3][6]);
            acc[3][7] = fmaf(a4.w, wB.w, acc[3][7]);
        }
        __syncthreads();
    }

    int nb = n0 + 8 * ng;
    float4 pbA = *(const float4*)(pb + nb);
    float4 pbB = *(const float4*)(pb + nb + 4);
    #pragma unroll
    for (int r = 0; r < 4; r++) {
        int mrow = 4 * mg + r;
        float4 o1, o2;
        o1.x = acc[r][0] + pbA.x; o1.y = acc[r][1] + pbA.y;
        o1.z = acc[r][2] + pbA.z; o1.w = acc[r][3] + pbA.w;
        o2.x = acc[r][4] + pbB.x; o2.y = acc[r][5] + pbB.y;
        o2.z = acc[r][6] + pbB.z; o2.w = acc[r][7] + pbB.w;
        *(float4*)(s_pol + (size_t)mrow * PSZ + nb)     = o1;
        *(float4*)(s_pol + (size_t)mrow * PSZ + nb + 4) = o2;
    }
}

// ---------------- stage 3: fast-LSTM ---------------------------------------
// CTA b: hidden cols [8b, 8b+8) x 4 gates. thread = (mg = tid>>3 -> 2 rows,
// cg = tid&7 -> 1 col, 4 gates via float4 weights).
__device__ __forceinline__ void f_phase3(
    const float* __restrict__ act, int poff, const float* __restrict__ W,
    int jj0, float* a_sm, float* w_sm, float acc[2][4])
{
    const int tid = threadIdx.x;
    const int cg  = tid & 7;
    const int mg  = tid >> 3;
    for (int k0 = 0; k0 < DD; k0 += 64) {
        #pragma unroll
        for (int r = 0; r < 16; r++) {       // a: 64m x 64k, pre-scaled by pol
            int i = r * 256 + tid;
            int mi = i >> 6, kk = i & 63, k = k0 + kk;
            a_sm[kk * 66 + mi] = act[mi * DD + k] * s_pol[(size_t)mi * PSZ + poff + k];
        }
        #pragma unroll
        for (int r = 0; r < 8; r++) {        // w: 32 (col,gate) x 64k
            int i = r * 256 + tid;
            int cf = i >> 6, kk = i & 63;
            int g = cf & 3, cgg = cf >> 2;
            int n = g * DD + jj0 + cgg;
            w_sm[kk * 36 + cf] = W[(size_t)n * DD + k0 + kk];
        }
        __syncthreads();
        #pragma unroll
        for (int kk = 0; kk < 64; kk++) {
            float2 a2 = *(const float2*)(a_sm + kk * 66 + 2 * mg);
            float4 w4 = *(const float4*)(w_sm + kk * 36 + 4 * cg);
            acc[0][0] = fmaf(a2.x, w4.x, acc[0][0]);
            acc[0][1] = fmaf(a2.x, w4.y, acc[0][1]);
            acc[0][2] = fmaf(a2.x, w4.z, acc[0][2]);
            acc[0][3] = fmaf(a2.x, w4.w, acc[0][3]);
            acc[1][0] = fmaf(a2.y, w4.x, acc[1][0]);
            acc[1][1] = fmaf(a2.y, w4.y, acc[1][1]);
            acc[1][2] = fmaf(a2.y, w4.z, acc[1][2]);
            acc[1][3] = fmaf(a2.y, w4.w, acc[1][3]);
        }
        __syncthreads();
    }
}

__device__ __forceinline__ void stage3(
    int l, int p, int t, const float* __restrict__ xt,
    const float* __restrict__ fwih, const float* __restrict__ fwhh,
    const float* __restrict__ fb, float* __restrict__ out, float* sm)
{
    float* a_sm = sm;            // [kk*66 + m], 64 x 66
    float* w_sm = sm + 4224;     // [kk*36 + cf], 64 x 36
    const int tid = threadIdx.x;
    const int jj0 = blockIdx.x * 8;
    const int cg  = tid & 7;
    const int mg  = tid >> 3;
    const int jj  = jj0 + cg;

    const float* xc    = (l == 0) ? xt : s_fh[p ^ 1][0];
    const float* fhOld = s_fh[p][l];

    float acc[2][4], g[2][4];
    #pragma unroll
    for (int r = 0; r < 2; r++)
        #pragma unroll
        for (int q = 0; q < 4; q++) acc[r][q] = 0.f;

    // phase 1: ig = (xc * p0) @ fwih.T
    f_phase3(xc, 0, fwih, jj0, a_sm, w_sm, acc);

    #pragma unroll
    for (int r = 0; r < 2; r++) {
        int m = 2 * mg + r;
        #pragma unroll
        for (int c2 = 0; c2 < 4; c2++) {
            int col = c2 * DD + jj;
            g[r][c2] = fmaf(acc[r][c2], s_pol[(size_t)m * PSZ + 2 * DD + col],
                            fb[col] * s_pol[(size_t)m * PSZ + 10 * DD + col]);
            acc[r][c2] = 0.f;
        }
    }

    // phase 2: hg = (fh_old * p1) @ fwhh.T
    f_phase3(fhOld, DD, fwhh, jj0, a_sm, w_sm, acc);

    #pragma unroll
    for (int r = 0; r < 2; r++) {
        int m = 2 * mg + r;
        float G0 = fmaf(acc[r][0], s_pol[(size_t)m * PSZ + 6 * DD + 0 * DD + jj], g[r][0]);
        float G1 = fmaf(acc[r][1], s_pol[(size_t)m * PSZ + 6 * DD + 1 * DD + jj], g[r][1]);
        float G2 = fmaf(acc[r][2], s_pol[(size_t)m * PSZ + 6 * DD + 2 * DD + jj], g[r][2]);
        float G3 = fmaf(acc[r][3], s_pol[(size_t)m * PSZ + 6 * DD + 3 * DD + jj], g[r][3]);
        float cO = s_fc[l][m * DD + jj];
        float cN = sigf(G1) * cO + sigf(G0) * tanhf(G2);
        float h  = sigf(G3) * tanhf(cN);
        s_fc[l][m * DD + jj] = cN;
        s_fh[p ^ 1][l][m * DD + jj] = h;
        if (l == 1) out[((size_t)t * BB + m) * DD + jj] = h;
    }
}

// ---------------- persistent kernel ----------------------------------------
__global__ void __launch_bounds__(NTHR, 1) alstm_persistent(Params P)
{
    __shared__ __align__(16) float sm[6600];
    const int tid = threadIdx.x;
    const int b   = blockIdx.x;

    // zero recurrent state (every replay)
    {
        int gtid = b * NTHR + tid, gsz = NCTA * NTHR;
        float* z1 = &s_ah[0][0][0];
        for (int i = gtid; i < 2 * NL * BB * AA; i += gsz) z1[i] = 0.f;
        float* z2 = &s_ac[0][0];
        for (int i = gtid; i < NL * BB * AA; i += gsz) z2[i] = 0.f;
        float* z3 = &s_fh[0][0][0];
        for (int i = gtid; i < 2 * NL * BB * DD; i += gsz) z3[i] = 0.f;
        float* z4 = &s_fc[0][0];
        for (int i = gtid; i < NL * BB * DD; i += gsz) z4[i] = 0.f;
    }
    grid_sync();

    for (int t = 0; t < TT; t++) {
        const int p = t & 1;
        const float* xt = P.x + (size_t)t * BB * DD;
        #pragma unroll
        for (int l = 0; l < NL; l++) {
            stage1(l, p, xt, P.awih[l], P.awhh[l], P.abih[l], P.abhh[l], sm);
            grid_sync();
            stage2(l, p, P.pw[l], P.pb[l], sm);
            grid_sync();
            stage3(l, p, t, xt, P.fwih[l], P.fwhh[l], P.fb[l], P.out, sm);
            grid_sync();
        }
    }
}

// ---------------- host launch ----------------------------------------------
extern "C" void kernel_launch(void* const* d_in, const int* in_sizes, int n_in,
                              void* d_out, int out_size)
{
    Params P;
    P.x       = (const float*)d_in[0];
    P.awih[0] = (const float*)d_in[1];  P.awih[1] = (const float*)d_in[10];
    P.awhh[0] = (const float*)d_in[2];  P.awhh[1] = (const float*)d_in[11];
    P.abih[0] = (const float*)d_in[3];  P.abih[1] = (const float*)d_in[12];
    P.abhh[0] = (const float*)d_in[4];  P.abhh[1] = (const float*)d_in[13];
    P.pw[0]   = (const float*)d_in[5];  P.pw[1]   = (const float*)d_in[14];
    P.pb[0]   = (const float*)d_in[6];  P.pb[1]   = (const float*)d_in[15];
    P.fwih[0] = (const float*)d_in[7];  P.fwih[1] = (const float*)d_in[16];
    P.fwhh[0] = (const float*)d_in[8];  P.fwhh[1] = (const float*)d_in[17];
    P.fb[0]   = (const float*)d_in[9];  P.fb[1]   = (const float*)d_in[18];
    P.out     = (float*)d_out;

    alstm_persistent<<<NCTA, NTHR>>>(P);
}

// round 5
// speedup vs baseline: 1.3389x; 1.3389x over previous
#include <cuda_runtime.h>
#include <math.h>

#define TT    512
#define BB    64
#define DD    1024
#define AA    128
#define AIN   2176           // D + D + A
#define KHALF 1152           // KTOT/2
#define NL    2
#define NCTA  256
#define NTHR  256

// ---------------- persistent state ----------------------------------------
__device__ float s_ah[2][NL][BB * AA];
__device__ float s_ahT[AA * BB];          // transposed ah_new (k-major) for stage2
__device__ float s_ac[NL][BB * AA];
__device__ float s_fh[2][NL][BB * DD];
__device__ float s_fc[NL][BB * DD];
__device__ float s_xp[BB * DD];           // xc * p0      (written by stage2 epilogue)
__device__ float s_hp[BB * DD];           // fh_old * p1
__device__ float s_p2[BB * 4 * DD];
__device__ float s_p3[BB * 4 * DD];
__device__ float s_b4[BB * 4 * DD];       // fb * p4

// ---------------- software grid barrier ------------------------------------
__device__ unsigned g_cnt = 0;
__device__ volatile unsigned g_gen = 0;

__device__ __forceinline__ void grid_sync() {
    __threadfence();
    __syncthreads();
    if (threadIdx.x == 0) {
        unsigned gen = g_gen;
        if (atomicAdd(&g_cnt, 1u) == NCTA - 1) {
            g_cnt = 0;
            __threadfence();
            g_gen = gen + 1;
        } else {
            while (g_gen == gen) { __nanosleep(64); }
        }
        __threadfence();
    }
    __syncthreads();
}

__device__ __forceinline__ float sigf(float x) { return 1.0f / (1.0f + expf(-x)); }

struct Params {
    const float* x;
    const float* awih[2]; const float* awhh[2];
    const float* abih[2]; const float* abhh[2];
    const float* pw[2];   const float* pb[2];
    const float* fwih[2]; const float* fwhh[2]; const float* fb[2];
    float* out;
};

// ---------------- stage 1: attention-LSTM ----------------------------------
// CTA b: j = b&127 (hidden col, 4 gate cols), mh = b>>7 (32-row half).
// Threads: kh = tid>>7 splits K in two halves; item = tid&127 -> (m, c).
// Partials combined via smem; pointwise fused; also writes transposed ahT.
__device__ __forceinline__ void stage1(
    int l, int p, const float* __restrict__ xt,
    const float* __restrict__ awih, const float* __restrict__ awhh,
    const float* __restrict__ abih, const float* __restrict__ abhh,
    float* sm)
{
    const int tid = threadIdx.x, b = blockIdx.x;
    const int j = b & 127, mh = b >> 7;
    const int kh = tid >> 7, item = tid & 127;
    const int m = item >> 2, c = item & 3;
    float* aS0 = sm;                 // 32 x 68
    float* aS1 = sm + 2176;          // 32 x 68
    float* wS0 = sm + 4352;          //  4 x 68
    float* wS1 = sm + 4624;          //  4 x 68
    float* red = sm + 4896;          // 128

    const float* xc     = (l == 0) ? xt : s_fh[p ^ 1][0];
    const float* fhOld  = s_fh[p][l];
    const float* ahSelf = s_ah[p][l];
    const float* ahOth  = (l == 0) ? s_ah[p][1] : s_ah[p ^ 1][0];

    float acc0 = 0.f, acc1 = 0.f;

    for (int ci = 0; ci < 18; ci++) {
        #pragma unroll
        for (int r = 0; r < 16; r++) {           // a: both halves' 32x64 chunks
            int idx = r * 256 + tid;
            int bf = idx >> 11, rem = idx & 2047;
            int mi = rem >> 6, kk = rem & 63;
            int k = bf * KHALF + ci * 64 + kk;
            int row = mh * 32 + mi;
            float v;
            if (k < DD)            v = xc[row * DD + k];
            else if (k < 2 * DD)   v = fhOld[row * DD + (k - DD)];
            else if (k < AIN)      v = ahOth[row * AA + (k - 2 * DD)];
            else                   v = ahSelf[row * AA + (k - AIN)];
            float* aS = bf ? aS1 : aS0;
            aS[mi * 68 + kk] = v;
        }
        #pragma unroll
        for (int r = 0; r < 2; r++) {            // w: both halves' 4x64 chunks
            int idx = r * 256 + tid;
            int bf = idx >> 8, rem = idx & 255;
            int cc = rem >> 6, kk = rem & 63;
            int k = bf * KHALF + ci * 64 + kk;
            int n = cc * AA + j;
            float v = (k < AIN) ? awih[(size_t)n * AIN + k]
                                : awhh[n * AA + (k - AIN)];
            float* wS = bf ? wS1 : wS0;
            wS[cc * 68 + kk] = v;
        }
        __syncthreads();
        const float4* av = (const float4*)((kh ? aS1 : aS0) + m * 68);
        const float4* wv = (const float4*)((kh ? wS1 : wS0) + c * 68);
        #pragma unroll
        for (int q = 0; q < 16; q++) {
            float4 a4 = av[q], w4 = wv[q];
            acc0 = fmaf(a4.x, w4.x, acc0);
            acc1 = fmaf(a4.y, w4.y, acc1);
            acc0 = fmaf(a4.z, w4.z, acc0);
            acc1 = fmaf(a4.w, w4.w, acc1);
        }
        __syncthreads();
    }

    float g = acc0 + acc1;
    if (kh == 1) red[item] = g;
    __syncthreads();
    if (kh == 0) {
        g += red[item] + abih[c * AA + j] + abhh[c * AA + j];
        const unsigned F = 0xffffffffu;
        int base = (tid & 31) & ~3;
        float gi = __shfl_sync(F, g, base + 0);
        float gf = __shfl_sync(F, g, base + 1);
        float gz = __shfl_sync(F, g, base + 2);
        float go = __shfl_sync(F, g, base + 3);
        if (c == 0) {
            int row = mh * 32 + m;
            float cO = s_ac[l][row * AA + j];
            float cN = sigf(gf) * cO + sigf(gi) * tanhf(gz);
            float h  = sigf(go) * tanhf(cN);
            s_ac[l][row * AA + j] = cN;
            s_ah[p ^ 1][l][row * AA + j] = h;
            s_ahT[j * BB + row] = h;
        }
    }
    __syncthreads();
}

// ---------------- stage 2: pol GEMM + segment-folding epilogue --------------
// 224 working CTAs x 64 cols. Thread tile 4m x 4n. Epilogue stores:
//   seg 0: xp = v*xc, seg 1: hp = v*fh_old, seg 2-5: p2, seg 6-9: p3,
//   seg 10-13: b4 = v*fb.
__device__ __forceinline__ void stage2(
    int l, int p, const float* __restrict__ xc,
    const float* __restrict__ pw, const float* __restrict__ pb,
    const float* __restrict__ fb, float* sm)
{
    const int b = blockIdx.x;
    if (b >= 224) return;
    float* aS = sm;                  // 64k x 68m
    float* wS = sm + 4352;           // 64k x 68n
    const int tid = threadIdx.x;
    const int n0 = b * 64;
    const int mg = tid & 15, ng = tid >> 4;
    const float* fhOld = s_fh[p][l];

    float acc[4][4];
    #pragma unroll
    for (int r = 0; r < 4; r++)
        #pragma unroll
        for (int q = 0; q < 4; q++) acc[r][q] = 0.f;

    for (int kc = 0; kc < AA; kc += 64) {
        #pragma unroll
        for (int r = 0; r < 16; r++) {
            int idx = r * 256 + tid, kk = idx >> 6, mi = idx & 63;
            aS[kk * 68 + mi] = s_ahT[(kc + kk) * BB + mi];
        }
        #pragma unroll
        for (int r = 0; r < 16; r++) {
            int idx = r * 256 + tid, nn = idx >> 6, kk = idx & 63;
            wS[kk * 68 + nn] = pw[(size_t)(n0 + nn) * AA + kc + kk];
        }
        __syncthreads();
        #pragma unroll
        for (int kk = 0; kk < 64; kk++) {
            float4 a4 = *(const float4*)(aS + kk * 68 + 4 * mg);
            float4 w4 = *(const float4*)(wS + kk * 68 + 4 * ng);
            acc[0][0] = fmaf(a4.x, w4.x, acc[0][0]);
            acc[0][1] = fmaf(a4.x, w4.y, acc[0][1]);
            acc[0][2] = fmaf(a4.x, w4.z, acc[0][2]);
            acc[0][3] = fmaf(a4.x, w4.w, acc[0][3]);
            acc[1][0] = fmaf(a4.y, w4.x, acc[1][0]);
            acc[1][1] = fmaf(a4.y, w4.y, acc[1][1]);
            acc[1][2] = fmaf(a4.y, w4.z, acc[1][2]);
            acc[1][3] = fmaf(a4.y, w4.w, acc[1][3]);
            acc[2][0] = fmaf(a4.z, w4.x, acc[2][0]);
            acc[2][1] = fmaf(a4.z, w4.y, acc[2][1]);
            acc[2][2] = fmaf(a4.z, w4.z, acc[2][2]);
            acc[2][3] = fmaf(a4.z, w4.w, acc[2][3]);
            acc[3][0] = fmaf(a4.w, w4.x, acc[3][0]);
            acc[3][1] = fmaf(a4.w, w4.y, acc[3][1]);
            acc[3][2] = fmaf(a4.w, w4.z, acc[3][2]);
            acc[3][3] = fmaf(a4.w, w4.w, acc[3][3]);
        }
        __syncthreads();
    }

    const int seg = n0 >> 10;
    const int nb  = n0 + 4 * ng;
    #pragma unroll
    for (int r = 0; r < 4; r++) {
        int m = 4 * mg + r;
        #pragma unroll
        for (int q = 0; q < 4; q++) {
            int col = nb + q;
            float v = acc[r][q] + pb[col];
            if (seg == 0)
                s_xp[m * DD + col] = v * xc[m * DD + col];
            else if (seg == 1)
                s_hp[m * DD + (col - DD)] = v * fhOld[m * DD + (col - DD)];
            else if (seg < 6)
                s_p2[m * 4 * DD + (col - 2 * DD)] = v;
            else if (seg < 10)
                s_p3[m * 4 * DD + (col - 6 * DD)] = v;
            else
                s_b4[m * 4 * DD + (col - 10 * DD)] = v * fb[col - 10 * DD];
        }
    }
}

// ---------------- stage 3: fast-LSTM ---------------------------------------
// 256 CTAs x 4 hidden cols. Thread: mg=tid>>3 (2 rows), cg=(tid>>1)&3 (col),
// gh=tid&1 (2 gates). Gates recombined with shfl_xor(1).
__device__ __forceinline__ void fgemm3(
    const float* __restrict__ src, const float* __restrict__ W,
    int jj0, float* aS, float* wS, float acc[2][2], int gh)
{
    const int tid = threadIdx.x;
    const int mg = tid >> 3, cg = (tid >> 1) & 3;
    for (int k0 = 0; k0 < DD; k0 += 64) {
        #pragma unroll
        for (int r = 0; r < 16; r++) {           // a: pure copy (pre-scaled)
            int idx = r * 256 + tid, mi = idx >> 6, kk = idx & 63;
            aS[kk * 66 + mi] = src[mi * DD + k0 + kk];
        }
        #pragma unroll
        for (int r = 0; r < 4; r++) {            // w: 16 (col,gate) x 64k
            int idx = r * 256 + tid, n16 = idx >> 6, kk = idx & 63;
            int g = n16 & 3, cl = n16 >> 2;
            wS[kk * 18 + cl * 4 + g] = W[(size_t)(g * DD + jj0 + cl) * DD + k0 + kk];
        }
        __syncthreads();
        #pragma unroll
        for (int kk = 0; kk < 64; kk++) {
            float2 a2 = *(const float2*)(aS + kk * 66 + 2 * mg);
            float2 w2 = *(const float2*)(wS + kk * 18 + 4 * cg + 2 * gh);
            acc[0][0] = fmaf(a2.x, w2.x, acc[0][0]);
            acc[0][1] = fmaf(a2.x, w2.y, acc[0][1]);
            acc[1][0] = fmaf(a2.y, w2.x, acc[1][0]);
            acc[1][1] = fmaf(a2.y, w2.y, acc[1][1]);
        }
        __syncthreads();
    }
}

__device__ __forceinline__ void stage3(
    int l, int p, int t,
    const float* __restrict__ fwih, const float* __restrict__ fwhh,
    float* __restrict__ out, float* sm)
{
    float* aS = sm;                  // 64 x 66
    float* wS = sm + 4224;           // 64 x 18
    const int tid = threadIdx.x, b = blockIdx.x;
    const int jj0 = b * 4;
    const int mg = tid >> 3, cg = (tid >> 1) & 3, gh = tid & 1;
    const int jj = jj0 + cg;

    float acc[2][2], g[2][2];
    #pragma unroll
    for (int r = 0; r < 2; r++)
        #pragma unroll
        for (int q = 0; q < 2; q++) acc[r][q] = 0.f;

    // phase 1: ig = xp @ fwih.T   (xp = xc*p0, pre-scaled by stage2)
    fgemm3(s_xp, fwih, jj0, aS, wS, acc, gh);
    #pragma unroll
    for (int r = 0; r < 2; r++) {
        int m = 2 * mg + r;
        #pragma unroll
        for (int q = 0; q < 2; q++) {
            int colg = (2 * gh + q) * DD + jj;
            g[r][q] = fmaf(acc[r][q], s_p2[m * 4 * DD + colg],
                           s_b4[m * 4 * DD + colg]);
            acc[r][q] = 0.f;
        }
    }

    // phase 2: hg = hp @ fwhh.T   (hp = fh_old*p1)
    fgemm3(s_hp, fwhh, jj0, aS, wS, acc, gh);

    const unsigned F = 0xffffffffu;
    #pragma unroll
    for (int r = 0; r < 2; r++) {
        int m = 2 * mg + r;
        float Ga = fmaf(acc[r][0], s_p3[m * 4 * DD + (2 * gh + 0) * DD + jj], g[r][0]);
        float Gb = fmaf(acc[r][1], s_p3[m * 4 * DD + (2 * gh + 1) * DD + jj], g[r][1]);
        float Gc = __shfl_xor_sync(F, Ga, 1);   // partner's first gate
        float Gd = __shfl_xor_sync(F, Gb, 1);   // partner's second gate
        if (gh == 0) {
            // Ga=i, Gb=f, Gc=g, Gd=o
            float cO = s_fc[l][m * DD + jj];
            float cN = sigf(Gb) * cO + sigf(Ga) * tanhf(Gc);
            float h  = sigf(Gd) * tanhf(cN);
            s_fc[l][m * DD + jj] = cN;
            s_fh[p ^ 1][l][m * DD + jj] = h;
            if (l == 1) out[((size_t)t * BB + m) * DD + jj] = h;
        }
    }
}

// ---------------- persistent kernel ----------------------------------------
__global__ void __launch_bounds__(NTHR, 2) alstm_persistent(Params P)
{
    __shared__ __align__(16) float sm[8704];
    const int tid = threadIdx.x, b = blockIdx.x;

    {   // zero recurrent state each replay
        int gtid = b * NTHR + tid, gsz = NCTA * NTHR;
        float* z1 = &s_ah[0][0][0];
        for (int i = gtid; i < 2 * NL * BB * AA; i += gsz) z1[i] = 0.f;
        float* z2 = &s_ac[0][0];
        for (int i = gtid; i < NL * BB * AA; i += gsz) z2[i] = 0.f;
        float* z3 = &s_fh[0][0][0];
        for (int i = gtid; i < 2 * NL * BB * DD; i += gsz) z3[i] = 0.f;
        float* z4 = &s_fc[0][0];
        for (int i = gtid; i < NL * BB * DD; i += gsz) z4[i] = 0.f;
    }
    grid_sync();

    for (int t = 0; t < TT; t++) {
        const int p = t & 1;
        const float* xt = P.x + (size_t)t * BB * DD;
        #pragma unroll
        for (int l = 0; l < NL; l++) {
            stage1(l, p, xt, P.awih[l], P.awhh[l], P.abih[l], P.abhh[l], sm);
            grid_sync();
            const float* xc = (l == 0) ? xt : s_fh[p ^ 1][0];
            stage2(l, p, xc, P.pw[l], P.pb[l], P.fb[l], sm);
            grid_sync();
            stage3(l, p, t, P.fwih[l], P.fwhh[l], P.out, sm);
            grid_sync();
        }
    }
}

// ---------------- host launch ----------------------------------------------
extern "C" void kernel_launch(void* const* d_in, const int* in_sizes, int n_in,
                              void* d_out, int out_size)
{
    Params P;
    P.x       = (const float*)d_in[0];
    P.awih[0] = (const float*)d_in[1];  P.awih[1] = (const float*)d_in[10];
    P.awhh[0] = (const float*)d_in[2];  P.awhh[1] = (const float*)d_in[11];
    P.abih[0] = (const float*)d_in[3];  P.abih[1] = (const float*)d_in[12];
    P.abhh[0] = (const float*)d_in[4];  P.abhh[1] = (const float*)d_in[13];
    P.pw[0]   = (const float*)d_in[5];  P.pw[1]   = (const float*)d_in[14];
    P.pb[0]   = (const float*)d_in[6];  P.pb[1]   = (const float*)d_in[15];
    P.fwih[0] = (const float*)d_in[7];  P.fwih[1] = (const float*)d_in[16];
    P.fwhh[0] = (const float*)d_in[8];  P.fwhh[1] = (const float*)d_in[17];
    P.fb[0]   = (const float*)d_in[9];  P.fb[1]   = (const float*)d_in[18];
    P.out     = (float*)d_out;

    alstm_persistent<<<NCTA, NTHR>>>(P);
}

// round 6
// speedup vs baseline: 1.3460x; 1.0053x over previous
#include <cuda_runtime.h>
#include <math.h>

#define TT    512
#define BB    64
#define DD    1024
#define AA    128
#define AIN   2176           // D + D + A
#define KHALF 1152           // KTOT/2
#define NL    2
#define NCTA  256
#define NTHR  256

// ---------------- persistent state ----------------------------------------
__device__ float s_ah[2][NL][BB * AA];
__device__ float s_ahT[AA * BB];          // transposed ah_new (k-major) for stage2
__device__ float s_ac[NL][BB * AA];
__device__ float s_fh[2][NL][BB * DD];
__device__ float s_fc[NL][BB * DD];
__device__ float s_xp[BB * DD];           // xc * p0      (written by stage2 epilogue)
__device__ float s_hp[BB * DD];           // fh_old * p1
__device__ float s_p2[BB * 4 * DD];
__device__ float s_p3[BB * 4 * DD];
__device__ float s_b4[BB * 4 * DD];       // fb * p4

// ---------------- software grid barrier ------------------------------------
__device__ unsigned g_cnt = 0;
__device__ volatile unsigned g_gen = 0;

__device__ __forceinline__ void grid_sync() {
    __threadfence();
    __syncthreads();
    if (threadIdx.x == 0) {
        unsigned gen = g_gen;
        if (atomicAdd(&g_cnt, 1u) == NCTA - 1) {
            g_cnt = 0;
            __threadfence();
            g_gen = gen + 1;
        } else {
            while (g_gen == gen) { __nanosleep(64); }
        }
        __threadfence();
    }
    __syncthreads();
}

__device__ __forceinline__ float sigf(float x) { return 1.0f / (1.0f + expf(-x)); }

struct Params {
    const float* x;
    const float* awih[2]; const float* awhh[2];
    const float* abih[2]; const float* abhh[2];
    const float* pw[2];   const float* pb[2];
    const float* fwih[2]; const float* fwhh[2]; const float* fb[2];
    float* out;
};

// ---------------- stage 1: attention-LSTM ----------------------------------
// CTA b: j = b&127 (hidden col, 4 gate cols), mh = b>>7 (32-row half).
// Threads: kh = tid>>7 splits K in two halves; item = tid&127 -> (m, c).
// Partials combined via smem; pointwise fused; also writes transposed ahT.
__device__ __forceinline__ void stage1(
    int l, int p, const float* __restrict__ xt,
    const float* __restrict__ awih, const float* __restrict__ awhh,
    const float* __restrict__ abih, const float* __restrict__ abhh,
    float* sm)
{
    const int tid = threadIdx.x, b = blockIdx.x;
    const int j = b & 127, mh = b >> 7;
    const int kh = tid >> 7, item = tid & 127;
    const int m = item >> 2, c = item & 3;
    float* aS0 = sm;                 // 32 x 68
    float* aS1 = sm + 2176;          // 32 x 68
    float* wS0 = sm + 4352;          //  4 x 68
    float* wS1 = sm + 4624;          //  4 x 68
    float* red = sm + 4896;          // 128

    const float* xc     = (l == 0) ? xt : s_fh[p ^ 1][0];
    const float* fhOld  = s_fh[p][l];
    const float* ahSelf = s_ah[p][l];
    const float* ahOth  = (l == 0) ? s_ah[p][1] : s_ah[p ^ 1][0];

    float acc0 = 0.f, acc1 = 0.f;

    for (int ci = 0; ci < 18; ci++) {
        #pragma unroll
        for (int r = 0; r < 16; r++) {           // a: both halves' 32x64 chunks
            int idx = r * 256 + tid;
            int bf = idx >> 11, rem = idx & 2047;
            int mi = rem >> 6, kk = rem & 63;
            int k = bf * KHALF + ci * 64 + kk;
            int row = mh * 32 + mi;
            float v;
            if (k < DD)            v = xc[row * DD + k];
            else if (k < 2 * DD)   v = fhOld[row * DD + (k - DD)];
            else if (k < AIN)      v = ahOth[row * AA + (k - 2 * DD)];
            else                   v = ahSelf[row * AA + (k - AIN)];
            float* aS = bf ? aS1 : aS0;
            aS[mi * 68 + kk] = v;
        }
        #pragma unroll
        for (int r = 0; r < 2; r++) {            // w: both halves' 4x64 chunks
            int idx = r * 256 + tid;
            int bf = idx >> 8, rem = idx & 255;
            int cc = rem >> 6, kk = rem & 63;
            int k = bf * KHALF + ci * 64 + kk;
            int n = cc * AA + j;
            float v = (k < AIN) ? awih[(size_t)n * AIN + k]
                                : awhh[n * AA + (k - AIN)];
            float* wS = bf ? wS1 : wS0;
            wS[cc * 68 + kk] = v;
        }
        __syncthreads();
        const float4* av = (const float4*)((kh ? aS1 : aS0) + m * 68);
        const float4* wv = (const float4*)((kh ? wS1 : wS0) + c * 68);
        #pragma unroll
        for (int q = 0; q < 16; q++) {
            float4 a4 = av[q], w4 = wv[q];
            acc0 = fmaf(a4.x, w4.x, acc0);
            acc1 = fmaf(a4.y, w4.y, acc1);
            acc0 = fmaf(a4.z, w4.z, acc0);
            acc1 = fmaf(a4.w, w4.w, acc1);
        }
        __syncthreads();
    }

    float g = acc0 + acc1;
    if (kh == 1) red[item] = g;
    __syncthreads();
    if (kh == 0) {
        g += red[item] + abih[c * AA + j] + abhh[c * AA + j];
        const unsigned F = 0xffffffffu;
        int base = (tid & 31) & ~3;
        float gi = __shfl_sync(F, g, base + 0);
        float gf = __shfl_sync(F, g, base + 1);
        float gz = __shfl_sync(F, g, base + 2);
        float go = __shfl_sync(F, g, base + 3);
        if (c == 0) {
            int row = mh * 32 + m;
            float cO = s_ac[l][row * AA + j];
            float cN = sigf(gf) * cO + sigf(gi) * tanhf(gz);
            float h  = sigf(go) * tanhf(cN);
            s_ac[l][row * AA + j] = cN;
            s_ah[p ^ 1][l][row * AA + j] = h;
            s_ahT[j * BB + row] = h;
        }
    }
    __syncthreads();
}

// ---------------- stage 2: pol GEMM + segment-folding epilogue --------------
// 224 working CTAs x 64 cols. Thread tile 4m x 4n. Epilogue stores:
//   seg 0: xp = v*xc, seg 1: hp = v*fh_old, seg 2-5: p2, seg 6-9: p3,
//   seg 10-13: b4 = v*fb.
__device__ __forceinline__ void stage2(
    int l, int p, const float* __restrict__ xc,
    const float* __restrict__ pw, const float* __restrict__ pb,
    const float* __restrict__ fb, float* sm)
{
    const int b = blockIdx.x;
    if (b >= 224) return;
    float* aS = sm;                  // 64k x 68m
    float* wS = sm + 4352;           // 64k x 68n
    const int tid = threadIdx.x;
    const int n0 = b * 64;
    const int mg = tid & 15, ng = tid >> 4;
    const float* fhOld = s_fh[p][l];

    float acc[4][4];
    #pragma unroll
    for (int r = 0; r < 4; r++)
        #pragma unroll
        for (int q = 0; q < 4; q++) acc[r][q] = 0.f;

    for (int kc = 0; kc < AA; kc += 64) {
        #pragma unroll
        for (int r = 0; r < 16; r++) {
            int idx = r * 256 + tid, kk = idx >> 6, mi = idx & 63;
            aS[kk * 68 + mi] = s_ahT[(kc + kk) * BB + mi];
        }
        #pragma unroll
        for (int r = 0; r < 16; r++) {
            int idx = r * 256 + tid, nn = idx >> 6, kk = idx & 63;
            wS[kk * 68 + nn] = pw[(size_t)(n0 + nn) * AA + kc + kk];
        }
        __syncthreads();
        #pragma unroll
        for (int kk = 0; kk < 64; kk++) {
            float4 a4 = *(const float4*)(aS + kk * 68 + 4 * mg);
            float4 w4 = *(const float4*)(wS + kk * 68 + 4 * ng);
            acc[0][0] = fmaf(a4.x, w4.x, acc[0][0]);
            acc[0][1] = fmaf(a4.x, w4.y, acc[0][1]);
            acc[0][2] = fmaf(a4.x, w4.z, acc[0][2]);
            acc[0][3] = fmaf(a4.x, w4.w, acc[0][3]);
            acc[1][0] = fmaf(a4.y, w4.x, acc[1][0]);
            acc[1][1] = fmaf(a4.y, w4.y, acc[1][1]);
            acc[1][2] = fmaf(a4.y, w4.z, acc[1][2]);
            acc[1][3] = fmaf(a4.y, w4.w, acc[1][3]);
            acc[2][0] = fmaf(a4.z, w4.x, acc[2][0]);
            acc[2][1] = fmaf(a4.z, w4.y, acc[2][1]);
            acc[2][2] = fmaf(a4.z, w4.z, acc[2][2]);
            acc[2][3] = fmaf(a4.z, w4.w, acc[2][3]);
            acc[3][0] = fmaf(a4.w, w4.x, acc[3][0]);
            acc[3][1] = fmaf(a4.w, w4.y, acc[3][1]);
            acc[3][2] = fmaf(a4.w, w4.z, acc[3][2]);
            acc[3][3] = fmaf(a4.w, w4.w, acc[3][3]);
        }
        __syncthreads();
    }

    const int seg = n0 >> 10;
    const int nb  = n0 + 4 * ng;
    #pragma unroll
    for (int r = 0; r < 4; r++) {
        int m = 4 * mg + r;
        #pragma unroll
        for (int q = 0; q < 4; q++) {
            int col = nb + q;
            float v = acc[r][q] + pb[col];
            if (seg == 0)
                s_xp[m * DD + col] = v * xc[m * DD + col];
            else if (seg == 1)
                s_hp[m * DD + (col - DD)] = v * fhOld[m * DD + (col - DD)];
            else if (seg < 6)
                s_p2[m * 4 * DD + (col - 2 * DD)] = v;
            else if (seg < 10)
                s_p3[m * 4 * DD + (col - 6 * DD)] = v;
            else
                s_b4[m * 4 * DD + (col - 10 * DD)] = v * fb[col - 10 * DD];
        }
    }
}

// ---------------- stage 3: fast-LSTM ---------------------------------------
// 256 CTAs x 4 hidden cols. Thread: mg=tid>>3 (2 rows), cg=(tid>>1)&3 (col),
// gh=tid&1 (2 gates). Gates recombined with shfl_xor(1).
__device__ __forceinline__ void fgemm3(
    const float* __restrict__ src, const float* __restrict__ W,
    int jj0, float* aS, float* wS, float acc[2][2], int gh)
{
    const int tid = threadIdx.x;
    const int mg = tid >> 3, cg = (tid >> 1) & 3;
    for (int k0 = 0; k0 < DD; k0 += 64) {
        #pragma unroll
        for (int r = 0; r < 16; r++) {           // a: pure copy (pre-scaled)
            int idx = r * 256 + tid, mi = idx >> 6, kk = idx & 63;
            aS[kk * 66 + mi] = src[mi * DD + k0 + kk];
        }
        #pragma unroll
        for (int r = 0; r < 4; r++) {            // w: 16 (col,gate) x 64k
            int idx = r * 256 + tid, n16 = idx >> 6, kk = idx & 63;
            int g = n16 & 3, cl = n16 >> 2;
            wS[kk * 18 + cl * 4 + g] = W[(size_t)(g * DD + jj0 + cl) * DD + k0 + kk];
        }
        __syncthreads();
        #pragma unroll
        for (int kk = 0; kk < 64; kk++) {
            float2 a2 = *(const float2*)(aS + kk * 66 + 2 * mg);
            float2 w2 = *(const float2*)(wS + kk * 18 + 4 * cg + 2 * gh);
            acc[0][0] = fmaf(a2.x, w2.x, acc[0][0]);
            acc[0][1] = fmaf(a2.x, w2.y, acc[0][1]);
            acc[1][0] = fmaf(a2.y, w2.x, acc[1][0]);
            acc[1][1] = fmaf(a2.y, w2.y, acc[1][1]);
        }
        __syncthreads();
    }
}

__device__ __forceinline__ void stage3(
    int l, int p, int t,
    const float* __restrict__ fwih, const float* __restrict__ fwhh,
    float* __restrict__ out, float* sm)
{
    float* aS = sm;                  // 64 x 66
    float* wS = sm + 4224;           // 64 x 18
    const int tid = threadIdx.x, b = blockIdx.x;
    const int jj0 = b * 4;
    const int mg = tid >> 3, cg = (tid >> 1) & 3, gh = tid & 1;
    const int jj = jj0 + cg;

    float acc[2][2], g[2][2];
    #pragma unroll
    for (int r = 0; r < 2; r++)
        #pragma unroll
        for (int q = 0; q < 2; q++) acc[r][q] = 0.f;

    // phase 1: ig = xp @ fwih.T   (xp = xc*p0, pre-scaled by stage2)
    fgemm3(s_xp, fwih, jj0, aS, wS, acc, gh);
    #pragma unroll
    for (int r = 0; r < 2; r++) {
        int m = 2 * mg + r;
        #pragma unroll
        for (int q = 0; q < 2; q++) {
            int colg = (2 * gh + q) * DD + jj;
            g[r][q] = fmaf(acc[r][q], s_p2[m * 4 * DD + colg],
                           s_b4[m * 4 * DD + colg]);
            acc[r][q] = 0.f;
        }
    }

    // phase 2: hg = hp @ fwhh.T   (hp = fh_old*p1)
    fgemm3(s_hp, fwhh, jj0, aS, wS, acc, gh);

    const unsigned F = 0xffffffffu;
    #pragma unroll
    for (int r = 0; r < 2; r++) {
        int m = 2 * mg + r;
        float Ga = fmaf(acc[r][0], s_p3[m * 4 * DD + (2 * gh + 0) * DD + jj], g[r][0]);
        float Gb = fmaf(acc[r][1], s_p3[m * 4 * DD + (2 * gh + 1) * DD + jj], g[r][1]);
        float Gc = __shfl_xor_sync(F, Ga, 1);   // partner's first gate
        float Gd = __shfl_xor_sync(F, Gb, 1);   // partner's second gate
        if (gh == 0) {
            // Ga=i, Gb=f, Gc=g, Gd=o
            float cO = s_fc[l][m * DD + jj];
            float cN = sigf(Gb) * cO + sigf(Ga) * tanhf(Gc);
            float h  = sigf(Gd) * tanhf(cN);
            s_fc[l][m * DD + jj] = cN;
            s_fh[p ^ 1][l][m * DD + jj] = h;
            if (l == 1) out[((size_t)t * BB + m) * DD + jj] = h;
        }
    }
}

// ---------------- persistent kernel ----------------------------------------
__global__ void __launch_bounds__(NTHR, 2) alstm_persistent(Params P)
{
    __shared__ __align__(16) float sm[8704];
    const int tid = threadIdx.x, b = blockIdx.x;

    {   // zero recurrent state each replay
        int gtid = b * NTHR + tid, gsz = NCTA * NTHR;
        float* z1 = &s_ah[0][0][0];
        for (int i = gtid; i < 2 * NL * BB * AA; i += gsz) z1[i] = 0.f;
        float* z2 = &s_ac[0][0];
        for (int i = gtid; i < NL * BB * AA; i += gsz) z2[i] = 0.f;
        float* z3 = &s_fh[0][0][0];
        for (int i = gtid; i < 2 * NL * BB * DD; i += gsz) z3[i] = 0.f;
        float* z4 = &s_fc[0][0];
        for (int i = gtid; i < NL * BB * DD; i += gsz) z4[i] = 0.f;
    }
    grid_sync();

    for (int t = 0; t < TT; t++) {
        const int p = t & 1;
        const float* xt = P.x + (size_t)t * BB * DD;
        #pragma unroll
        for (int l = 0; l < NL; l++) {
            stage1(l, p, xt, P.awih[l], P.awhh[l], P.abih[l], P.abhh[l], sm);
            grid_sync();
            const float* xc = (l == 0) ? xt : s_fh[p ^ 1][0];
            stage2(l, p, xc, P.pw[l], P.pb[l], P.fb[l], sm);
            grid_sync();
            stage3(l, p, t, P.fwih[l], P.fwhh[l], P.out, sm);
            grid_sync();
        }
    }
}

// ---------------- host launch ----------------------------------------------
extern "C" void kernel_launch(void* const* d_in, const int* in_sizes, int n_in,
                              void* d_out, int out_size)
{
    Params P;
    P.x       = (const float*)d_in[0];
    P.awih[0] = (const float*)d_in[1];  P.awih[1] = (const float*)d_in[10];
    P.awhh[0] = (const float*)d_in[2];  P.awhh[1] = (const float*)d_in[11];
    P.abih[0] = (const float*)d_in[3];  P.abih[1] = (const float*)d_in[12];
    P.abhh[0] = (const float*)d_in[4];  P.abhh[1] = (const float*)d_in[13];
    P.pw[0]   = (const float*)d_in[5];  P.pw[1]   = (const float*)d_in[14];
    P.pb[0]   = (const float*)d_in[6];  P.pb[1]   = (const float*)d_in[15];
    P.fwih[0] = (const float*)d_in[7];  P.fwih[1] = (const float*)d_in[16];
    P.fwhh[0] = (const float*)d_in[8];  P.fwhh[1] = (const float*)d_in[17];
    P.fb[0]   = (const float*)d_in[9];  P.fb[1]   = (const float*)d_in[18];
    P.out     = (float*)d_out;

    alstm_persistent<<<NCTA, NTHR>>>(P);
}

// round 7
// speedup vs baseline: 1.6158x; 1.2004x over previous
#include <cuda_runtime.h>
#include <math.h>

#define TT    512
#define BB    64
#define DD    1024
#define AA    128
#define AIN   2176           // D + D + A
#define KHALF 1152           // KTOT/2
#define NL    2
#define NCTA  256
#define NTHR  256
#define NG4   4096           // 4 gates * D

// ---------------- persistent state ----------------------------------------
__device__ float s_ah[2][NL][BB * AA];
__device__ float s_ahT[AA * BB];          // transposed ah_new (k-major) for stage2
__device__ float s_ac[NL][BB * AA];
__device__ float s_fh[2][NL][BB * DD];
__device__ float s_fc[NL][BB * DD];
__device__ float s_xp[BB * DD];           // xc * p0      (stage2 epilogue)
__device__ float s_hp[BB * DD];           // fh_old * p1
__device__ float s_p2[BB * NG4];
__device__ float s_p3[BB * NG4];
__device__ float s_b4[BB * NG4];          // fb * p4
__device__ float s_pt[2][4][BB][NG4];     // K-split GEMM partials (8 MB)

// ---------------- software grid barrier ------------------------------------
__device__ unsigned g_cnt = 0;
__device__ volatile unsigned g_gen = 0;

__device__ __forceinline__ void grid_sync() {
    __threadfence();
    __syncthreads();
    if (threadIdx.x == 0) {
        unsigned gen = g_gen;
        if (atomicAdd(&g_cnt, 1u) == NCTA - 1) {
            g_cnt = 0;
            __threadfence();
            g_gen = gen + 1;
        } else {
            while (g_gen == gen) { __nanosleep(64); }
        }
        __threadfence();
    }
    __syncthreads();
}

__device__ __forceinline__ float sigf(float x) { return 1.0f / (1.0f + expf(-x)); }

struct Params {
    const float* x;
    const float* awih[2]; const float* awhh[2];
    const float* abih[2]; const float* abhh[2];
    const float* pw[2];   const float* pb[2];
    const float* fwih[2]; const float* fwhh[2]; const float* fb[2];
    float* out;
};

// ---------------- stage 1: attention-LSTM (unchanged) ----------------------
__device__ __forceinline__ void stage1(
    int l, int p, const float* __restrict__ xt,
    const float* __restrict__ awih, const float* __restrict__ awhh,
    const float* __restrict__ abih, const float* __restrict__ abhh,
    float* sm)
{
    const int tid = threadIdx.x, b = blockIdx.x;
    const int j = b & 127, mh = b >> 7;
    const int kh = tid >> 7, item = tid & 127;
    const int m = item >> 2, c = item & 3;
    float* aS0 = sm;
    float* aS1 = sm + 2176;
    float* wS0 = sm + 4352;
    float* wS1 = sm + 4624;
    float* red = sm + 4896;

    const float* xc     = (l == 0) ? xt : s_fh[p ^ 1][0];
    const float* fhOld  = s_fh[p][l];
    const float* ahSelf = s_ah[p][l];
    const float* ahOth  = (l == 0) ? s_ah[p][1] : s_ah[p ^ 1][0];

    float acc0 = 0.f, acc1 = 0.f;

    for (int ci = 0; ci < 18; ci++) {
        #pragma unroll
        for (int r = 0; r < 16; r++) {
            int idx = r * 256 + tid;
            int bf = idx >> 11, rem = idx & 2047;
            int mi = rem >> 6, kk = rem & 63;
            int k = bf * KHALF + ci * 64 + kk;
            int row = mh * 32 + mi;
            float v;
            if (k < DD)            v = xc[row * DD + k];
            else if (k < 2 * DD)   v = fhOld[row * DD + (k - DD)];
            else if (k < AIN)      v = ahOth[row * AA + (k - 2 * DD)];
            else                   v = ahSelf[row * AA + (k - AIN)];
            float* aS = bf ? aS1 : aS0;
            aS[mi * 68 + kk] = v;
        }
        #pragma unroll
        for (int r = 0; r < 2; r++) {
            int idx = r * 256 + tid;
            int bf = idx >> 8, rem = idx & 255;
            int cc = rem >> 6, kk = rem & 63;
            int k = bf * KHALF + ci * 64 + kk;
            int n = cc * AA + j;
            float v = (k < AIN) ? awih[(size_t)n * AIN + k]
                                : awhh[n * AA + (k - AIN)];
            float* wS = bf ? wS1 : wS0;
            wS[cc * 68 + kk] = v;
        }
        __syncthreads();
        const float4* av = (const float4*)((kh ? aS1 : aS0) + m * 68);
        const float4* wv = (const float4*)((kh ? wS1 : wS0) + c * 68);
        #pragma unroll
        for (int q = 0; q < 16; q++) {
            float4 a4 = av[q], w4 = wv[q];
            acc0 = fmaf(a4.x, w4.x, acc0);
            acc1 = fmaf(a4.y, w4.y, acc1);
            acc0 = fmaf(a4.z, w4.z, acc0);
            acc1 = fmaf(a4.w, w4.w, acc1);
        }
        __syncthreads();
    }

    float g = acc0 + acc1;
    if (kh == 1) red[item] = g;
    __syncthreads();
    if (kh == 0) {
        g += red[item] + abih[c * AA + j] + abhh[c * AA + j];
        const unsigned F = 0xffffffffu;
        int base = (tid & 31) & ~3;
        float gi = __shfl_sync(F, g, base + 0);
        float gf = __shfl_sync(F, g, base + 1);
        float gz = __shfl_sync(F, g, base + 2);
        float go = __shfl_sync(F, g, base + 3);
        if (c == 0) {
            int row = mh * 32 + m;
            float cO = s_ac[l][row * AA + j];
            float cN = sigf(gf) * cO + sigf(gi) * tanhf(gz);
            float h  = sigf(go) * tanhf(cN);
            s_ac[l][row * AA + j] = cN;
            s_ah[p ^ 1][l][row * AA + j] = h;
            s_ahT[j * BB + row] = h;
        }
    }
    __syncthreads();
}

// ---------------- stage 2: pol GEMM + segment-folding epilogue --------------
__device__ __forceinline__ void stage2(
    int l, int p, const float* __restrict__ xc,
    const float* __restrict__ pw, const float* __restrict__ pb,
    const float* __restrict__ fb, float* sm)
{
    const int b = blockIdx.x;
    if (b >= 224) return;
    float* aS = sm;
    float* wS = sm + 4352;
    const int tid = threadIdx.x;
    const int n0 = b * 64;
    const int mg = tid & 15, ng = tid >> 4;
    const float* fhOld = s_fh[p][l];

    float acc[4][4];
    #pragma unroll
    for (int r = 0; r < 4; r++)
        #pragma unroll
        for (int q = 0; q < 4; q++) acc[r][q] = 0.f;

    for (int kc = 0; kc < AA; kc += 64) {
        #pragma unroll
        for (int r = 0; r < 16; r++) {
            int idx = r * 256 + tid, kk = idx >> 6, mi = idx & 63;
            aS[kk * 68 + mi] = s_ahT[(kc + kk) * BB + mi];
        }
        #pragma unroll
        for (int r = 0; r < 16; r++) {
            int idx = r * 256 + tid, nn = idx >> 6, kk = idx & 63;
            wS[kk * 68 + nn] = pw[(size_t)(n0 + nn) * AA + kc + kk];
        }
        __syncthreads();
        #pragma unroll
        for (int kk = 0; kk < 64; kk++) {
            float4 a4 = *(const float4*)(aS + kk * 68 + 4 * mg);
            float4 w4 = *(const float4*)(wS + kk * 68 + 4 * ng);
            acc[0][0] = fmaf(a4.x, w4.x, acc[0][0]);
            acc[0][1] = fmaf(a4.x, w4.y, acc[0][1]);
            acc[0][2] = fmaf(a4.x, w4.z, acc[0][2]);
            acc[0][3] = fmaf(a4.x, w4.w, acc[0][3]);
            acc[1][0] = fmaf(a4.y, w4.x, acc[1][0]);
            acc[1][1] = fmaf(a4.y, w4.y, acc[1][1]);
            acc[1][2] = fmaf(a4.y, w4.z, acc[1][2]);
            acc[1][3] = fmaf(a4.y, w4.w, acc[1][3]);
            acc[2][0] = fmaf(a4.z, w4.x, acc[2][0]);
            acc[2][1] = fmaf(a4.z, w4.y, acc[2][1]);
            acc[2][2] = fmaf(a4.z, w4.z, acc[2][2]);
            acc[2][3] = fmaf(a4.z, w4.w, acc[2][3]);
            acc[3][0] = fmaf(a4.w, w4.x, acc[3][0]);
            acc[3][1] = fmaf(a4.w, w4.y, acc[3][1]);
            acc[3][2] = fmaf(a4.w, w4.z, acc[3][2]);
            acc[3][3] = fmaf(a4.w, w4.w, acc[3][3]);
        }
        __syncthreads();
    }

    const int seg = n0 >> 10;
    const int nb  = n0 + 4 * ng;
    #pragma unroll
    for (int r = 0; r < 4; r++) {
        int m = 4 * mg + r;
        #pragma unroll
        for (int q = 0; q < 4; q++) {
            int col = nb + q;
            float v = acc[r][q] + pb[col];
            if (seg == 0)
                s_xp[m * DD + col] = v * xc[m * DD + col];
            else if (seg == 1)
                s_hp[m * DD + (col - DD)] = v * fhOld[m * DD + (col - DD)];
            else if (seg < 6)
                s_p2[m * NG4 + (col - 2 * DD)] = v;
            else if (seg < 10)
                s_p3[m * NG4 + (col - 6 * DD)] = v;
            else
                s_b4[m * NG4 + (col - 10 * DD)] = v * fb[col - 10 * DD];
        }
    }
}

// ---------------- stage 3a: fast-LSTM gate GEMMs (K-split) ------------------
// 256 CTAs = 2 phases (ig|hg) x 32 N-tiles (128 colgates) x 4 K-chunks (256).
// Thread tile 4m x 8n -> 48B LDS per 32 FFMA (1.5 B/FMA).
__device__ __forceinline__ void stage3_gemm(
    const float* __restrict__ fwih, const float* __restrict__ fwhh, float* sm)
{
    const int tid = threadIdx.x, b = blockIdx.x;
    const int ph = b >> 7;
    const int nt = (b & 127) >> 2;       // 0..31
    const int kc = b & 3;                // 0..3
    const int n0 = nt * 128;             // colgate base (g-major flat)
    const int kb = kc * 256;

    const float* src = ph ? s_hp : s_xp;
    const float* W   = ph ? fwhh : fwih;

    float* aS = sm;                      // [kk*68 + m], 32 x 68
    float* wS = sm + 2176;               // [kk*132 + nn], 32 x 132

    const int mg = tid & 15, ng = tid >> 4;

    float acc[4][8];
    #pragma unroll
    for (int r = 0; r < 4; r++)
        #pragma unroll
        for (int q = 0; q < 8; q++) acc[r][q] = 0.f;

    for (int k0 = 0; k0 < 256; k0 += 32) {
        #pragma unroll
        for (int r = 0; r < 8; r++) {        // a: 64m x 32k
            int idx = r * 256 + tid;
            int kk = idx & 31, mi = idx >> 5;
            aS[kk * 68 + mi] = src[mi * DD + kb + k0 + kk];
        }
        #pragma unroll
        for (int r = 0; r < 16; r++) {       // w: 128n x 32k
            int idx = r * 256 + tid;
            int kk = idx & 31, nn = idx >> 5;
            wS[kk * 132 + nn] = W[(size_t)(n0 + nn) * DD + kb + k0 + kk];
        }
        __syncthreads();
        #pragma unroll
        for (int kk = 0; kk < 32; kk++) {
            float4 a4 = *(const float4*)(aS + kk * 68 + 4 * mg);
            float4 wA = *(const float4*)(wS + kk * 132 + 8 * ng);
            float4 wB = *(const float4*)(wS + kk * 132 + 8 * ng + 4);
            acc[0][0] = fmaf(a4.x, wA.x, acc[0][0]);
            acc[0][1] = fmaf(a4.x, wA.y, acc[0][1]);
            acc[0][2] = fmaf(a4.x, wA.z, acc[0][2]);
            acc[0][3] = fmaf(a4.x, wA.w, acc[0][3]);
            acc[0][4] = fmaf(a4.x, wB.x, acc[0][4]);
            acc[0][5] = fmaf(a4.x, wB.y, acc[0][5]);
            acc[0][6] = fmaf(a4.x, wB.z, acc[0][6]);
            acc[0][7] = fmaf(a4.x, wB.w, acc[0][7]);
            acc[1][0] = fmaf(a4.y, wA.x, acc[1][0]);
            acc[1][1] = fmaf(a4.y, wA.y, acc[1][1]);
            acc[1][2] = fmaf(a4.y, wA.z, acc[1][2]);
            acc[1][3] = fmaf(a4.y, wA.w, acc[1][3]);
            acc[1][4] = fmaf(a4.y, wB.x, acc[1][4]);
            acc[1][5] = fmaf(a4.y, wB.y, acc[1][5]);
            acc[1][6] = fmaf(a4.y, wB.z, acc[1][6]);
            acc[1][7] = fmaf(a4.y, wB.w, acc[1][7]);
            acc[2][0] = fmaf(a4.z, wA.x, acc[2][0]);
            acc[2][1] = fmaf(a4.z, wA.y, acc[2][1]);
            acc[2][2] = fmaf(a4.z, wA.z, acc[2][2]);
            acc[2][3] = fmaf(a4.z, wA.w, acc[2][3]);
            acc[2][4] = fmaf(a4.z, wB.x, acc[2][4]);
            acc[2][5] = fmaf(a4.z, wB.y, acc[2][5]);
            acc[2][6] = fmaf(a4.z, wB.z, acc[2][6]);
            acc[2][7] = fmaf(a4.z, wB.w, acc[2][7]);
            acc[3][0] = fmaf(a4.w, wA.x, acc[3][0]);
            acc[3][1] = fmaf(a4.w, wA.y, acc[3][1]);
            acc[3][2] = fmaf(a4.w, wA.z, acc[3][2]);
            acc[3][3] = fmaf(a4.w, wA.w, acc[3][3]);
            acc[3][4] = fmaf(a4.w, wB.x, acc[3][4]);
            acc[3][5] = fmaf(a4.w, wB.y, acc[3][5]);
            acc[3][6] = fmaf(a4.w, wB.z, acc[3][6]);
            acc[3][7] = fmaf(a4.w, wB.w, acc[3][7]);
        }
        __syncthreads();
    }

    float* dst = &s_pt[ph][kc][0][0];
    #pragma unroll
    for (int r = 0; r < 4; r++) {
        int m = 4 * mg + r;
        float4 o1, o2;
        o1.x = acc[r][0]; o1.y = acc[r][1]; o1.z = acc[r][2]; o1.w = acc[r][3];
        o2.x = acc[r][4]; o2.y = acc[r][5]; o2.z = acc[r][6]; o2.w = acc[r][7];
        *(float4*)(dst + (size_t)m * NG4 + n0 + 8 * ng)     = o1;
        *(float4*)(dst + (size_t)m * NG4 + n0 + 8 * ng + 4) = o2;
    }
}

// ---------------- stage 3b: partial reduce + pointwise LSTM -----------------
// 256 CTAs x 4 cols. thread: m = tid>>2, c = tid&3.
__device__ __forceinline__ void stage3b(
    int l, int p, int t, float* __restrict__ out)
{
    const int tid = threadIdx.x, b = blockIdx.x;
    const int m = tid >> 2, col = b * 4 + (tid & 3);

    float G[4];
    #pragma unroll
    for (int g = 0; g < 4; g++) {
        size_t cg = (size_t)m * NG4 + g * DD + col;
        float ig = s_pt[0][0][0][cg] + s_pt[0][1][0][cg]
                 + s_pt[0][2][0][cg] + s_pt[0][3][0][cg];
        float hg = s_pt[1][0][0][cg] + s_pt[1][1][0][cg]
                 + s_pt[1][2][0][cg] + s_pt[1][3][0][cg];
        G[g] = fmaf(ig, s_p2[cg], s_b4[cg]) + hg * s_p3[cg];
    }
    float cO = s_fc[l][m * DD + col];
    float cN = sigf(G[1]) * cO + sigf(G[0]) * tanhf(G[2]);
    float h  = sigf(G[3]) * tanhf(cN);
    s_fc[l][m * DD + col] = cN;
    s_fh[p ^ 1][l][m * DD + col] = h;
    if (l == 1) out[((size_t)t * BB + m) * DD + col] = h;
}

// ---------------- persistent kernel ----------------------------------------
__global__ void __launch_bounds__(NTHR, 2) alstm_persistent(Params P)
{
    __shared__ __align__(16) float sm[8704];
    const int tid = threadIdx.x, b = blockIdx.x;

    {   // zero recurrent state each replay
        int gtid = b * NTHR + tid, gsz = NCTA * NTHR;
        float* z1 = &s_ah[0][0][0];
        for (int i = gtid; i < 2 * NL * BB * AA; i += gsz) z1[i] = 0.f;
        float* z2 = &s_ac[0][0];
        for (int i = gtid; i < NL * BB * AA; i += gsz) z2[i] = 0.f;
        float* z3 = &s_fh[0][0][0];
        for (int i = gtid; i < 2 * NL * BB * DD; i += gsz) z3[i] = 0.f;
        float* z4 = &s_fc[0][0];
        for (int i = gtid; i < NL * BB * DD; i += gsz) z4[i] = 0.f;
    }
    grid_sync();

    for (int t = 0; t < TT; t++) {
        const int p = t & 1;
        const float* xt = P.x + (size_t)t * BB * DD;
        #pragma unroll
        for (int l = 0; l < NL; l++) {
            stage1(l, p, xt, P.awih[l], P.awhh[l], P.abih[l], P.abhh[l], sm);
            grid_sync();
            const float* xc = (l == 0) ? xt : s_fh[p ^ 1][0];
            stage2(l, p, xc, P.pw[l], P.pb[l], P.fb[l], sm);
            grid_sync();
            stage3_gemm(P.fwih[l], P.fwhh[l], sm);
            grid_sync();
            stage3b(l, p, t, P.out);
            grid_sync();
        }
    }
}

// ---------------- host launch ----------------------------------------------
extern "C" void kernel_launch(void* const* d_in, const int* in_sizes, int n_in,
                              void* d_out, int out_size)
{
    Params P;
    P.x       = (const float*)d_in[0];
    P.awih[0] = (const float*)d_in[1];  P.awih[1] = (const float*)d_in[10];
    P.awhh[0] = (const float*)d_in[2];  P.awhh[1] = (const float*)d_in[11];
    P.abih[0] = (const float*)d_in[3];  P.abih[1] = (const float*)d_in[12];
    P.abhh[0] = (const float*)d_in[4];  P.abhh[1] = (const float*)d_in[13];
    P.pw[0]   = (const float*)d_in[5];  P.pw[1]   = (const float*)d_in[14];
    P.pb[0]   = (const float*)d_in[6];  P.pb[1]   = (const float*)d_in[15];
    P.fwih[0] = (const float*)d_in[7];  P.fwih[1] = (const float*)d_in[16];
    P.fwhh[0] = (const float*)d_in[8];  P.fwhh[1] = (const float*)d_in[17];
    P.fb[0]   = (const float*)d_in[9];  P.fb[1]   = (const float*)d_in[18];
    P.out     = (float*)d_out;

    alstm_persistent<<<NCTA, NTHR>>>(P);
}

// round 8
// speedup vs baseline: 2.4334x; 1.5061x over previous
#include <cuda_runtime.h>
#include <math.h>

#define TT    512
#define BB    64
#define DD    1024
#define AA    128
#define AIN   2176           // D + D + A
#define KHALF 1152           // KTOT/2
#define NL    2
#define NCTA  256
#define NTHR  256
#define NG4   4096           // 4 gates * D
#define SMEM_FLOATS 17408    // max over stages (stage2)
#define SMEM_BYTES  (SMEM_FLOATS * 4)

// ---------------- persistent state ----------------------------------------
__device__ float s_ah[2][NL][BB * AA];
__device__ float s_ahT[AA * BB];          // transposed ah_new (k-major) for stage2
__device__ float s_ac[NL][BB * AA];
__device__ float s_fh[2][NL][BB * DD];
__device__ float s_fc[NL][BB * DD];
__device__ float s_xp[BB * DD];           // xc * p0      (stage2 epilogue)
__device__ float s_hp[BB * DD];           // fh_old * p1
__device__ float s_p2[BB * NG4];
__device__ float s_p3[BB * NG4];
__device__ float s_b4[BB * NG4];          // fb * p4
__device__ float s_pt[2][4][BB][NG4];     // K-split GEMM partials

// ---------------- cp.async helpers ------------------------------------------
__device__ __forceinline__ void cp16(float* dst, const float* src) {
    unsigned d = (unsigned)__cvta_generic_to_shared(dst);
    asm volatile("cp.async.cg.shared.global [%0], [%1], 16;" :: "r"(d), "l"(src));
}
__device__ __forceinline__ void cp_commit() {
    asm volatile("cp.async.commit_group;" ::: "memory");
}
__device__ __forceinline__ void cp_wait0() {
    asm volatile("cp.async.wait_group 0;" ::: "memory");
}
__device__ __forceinline__ void cp_wait1() {
    asm volatile("cp.async.wait_group 1;" ::: "memory");
}

// ---------------- software grid barrier ------------------------------------
__device__ unsigned g_cnt = 0;
__device__ volatile unsigned g_gen = 0;

__device__ __forceinline__ void grid_sync() {
    __threadfence();
    __syncthreads();
    if (threadIdx.x == 0) {
        unsigned gen = g_gen;
        if (atomicAdd(&g_cnt, 1u) == NCTA - 1) {
            g_cnt = 0;
            __threadfence();
            g_gen = gen + 1;
        } else {
            while (g_gen == gen) { __nanosleep(64); }
        }
        __threadfence();
    }
    __syncthreads();
}

__device__ __forceinline__ float sigf(float x) { return 1.0f / (1.0f + expf(-x)); }

struct Params {
    const float* x;
    const float* awih[2]; const float* awhh[2];
    const float* abih[2]; const float* abhh[2];
    const float* pw[2];   const float* pb[2];
    const float* fwih[2]; const float* fwhh[2]; const float* fb[2];
    float* out;
};

// ============================ stage 1 =======================================
// CTA: j = b&127, mh = b>>7 (32-row half). K halved across threads (kh).
// smem per buffer: aS0[32*68] aS1[32*68] wS0[4*68] wS1[4*68] = 4896 floats.
// red at 2*4896 = 9792 (128 floats).
__device__ __forceinline__ void s1_fill(
    int ci, float* buf, int mh, int j,
    const float* __restrict__ xc, const float* __restrict__ fhOld,
    const float* __restrict__ ahOth, const float* __restrict__ ahSelf,
    const float* __restrict__ awih, const float* __restrict__ awhh)
{
    const int tid = threadIdx.x;
    #pragma unroll
    for (int r = 0; r < 4; r++) {
        int idx = r * 256 + tid;
        int bf = idx >> 9, rem = idx & 511;
        int mi = rem >> 4, uu = rem & 15;
        int k = bf * KHALF + ci * 64 + uu * 4;
        int row = mh * 32 + mi;
        const float* src;
        if (k < DD)            src = xc + row * DD + k;
        else if (k < 2 * DD)   src = fhOld + row * DD + (k - DD);
        else if (k < AIN)      src = ahOth + row * AA + (k - 2 * DD);
        else                   src = ahSelf + row * AA + (k - AIN);
        cp16(buf + bf * 2176 + mi * 68 + uu * 4, src);
    }
    if (tid < 128) {
        int bf = tid >> 6, rem = tid & 63;
        int cc = rem >> 4, uu = rem & 15;
        int k = bf * KHALF + ci * 64 + uu * 4;
        int n = cc * AA + j;
        const float* src = (k < AIN) ? awih + (size_t)n * AIN + k
                                     : awhh + n * AA + (k - AIN);
        cp16(buf + 4352 + bf * 272 + cc * 68 + uu * 4, src);
    }
}

__device__ __forceinline__ void stage1(
    int l, int p, const float* __restrict__ xt,
    const float* __restrict__ awih, const float* __restrict__ awhh,
    const float* __restrict__ abih, const float* __restrict__ abhh,
    float* sm)
{
    const int tid = threadIdx.x, b = blockIdx.x;
    const int j = b & 127, mh = b >> 7;
    const int kh = tid >> 7, item = tid & 127;
    const int m = item >> 2, c = item & 3;
    float* red = sm + 9792;

    const float* xc     = (l == 0) ? xt : s_fh[p ^ 1][0];
    const float* fhOld  = s_fh[p][l];
    const float* ahSelf = s_ah[p][l];
    const float* ahOth  = (l == 0) ? s_ah[p][1] : s_ah[p ^ 1][0];

    float acc0 = 0.f, acc1 = 0.f;

    s1_fill(0, sm, mh, j, xc, fhOld, ahOth, ahSelf, awih, awhh);
    cp_commit();

    for (int ci = 0; ci < 18; ci++) {
        float* buf = sm + (ci & 1) * 4896;
        if (ci < 17) {
            s1_fill(ci + 1, sm + ((ci + 1) & 1) * 4896, mh, j,
                    xc, fhOld, ahOth, ahSelf, awih, awhh);
            cp_commit();
            cp_wait1();
        } else {
            cp_wait0();
        }
        __syncthreads();
        const float4* av = (const float4*)(buf + kh * 2176 + m * 68);
        const float4* wv = (const float4*)(buf + 4352 + kh * 272 + c * 68);
        #pragma unroll
        for (int q = 0; q < 16; q++) {
            float4 a4 = av[q], w4 = wv[q];
            acc0 = fmaf(a4.x, w4.x, acc0);
            acc1 = fmaf(a4.y, w4.y, acc1);
            acc0 = fmaf(a4.z, w4.z, acc0);
            acc1 = fmaf(a4.w, w4.w, acc1);
        }
        __syncthreads();
    }

    float g = acc0 + acc1;
    if (kh == 1) red[item] = g;
    __syncthreads();
    if (kh == 0) {
        g += red[item] + abih[c * AA + j] + abhh[c * AA + j];
        const unsigned F = 0xffffffffu;
        int base = (tid & 31) & ~3;
        float gi = __shfl_sync(F, g, base + 0);
        float gf = __shfl_sync(F, g, base + 1);
        float gz = __shfl_sync(F, g, base + 2);
        float go = __shfl_sync(F, g, base + 3);
        if (c == 0) {
            int row = mh * 32 + m;
            float cO = s_ac[l][row * AA + j];
            float cN = sigf(gf) * cO + sigf(gi) * tanhf(gz);
            float h  = sigf(go) * tanhf(cN);
            s_ac[l][row * AA + j] = cN;
            s_ah[p ^ 1][l][row * AA + j] = h;
            s_ahT[j * BB + row] = h;
        }
    }
    __syncthreads();
}

// ============================ stage 2 =======================================
// 224 working CTAs x 64 n. a from s_ahT (k-major [kk][m], stride 68),
// w n-major ([nn][kk], stride 68). Both K-chunks prefetched up front.
__device__ __forceinline__ void s2_fill(
    int kc, float* buf, int n0, const float* __restrict__ pw)
{
    const int tid = threadIdx.x;
    float* aS = buf;
    float* wS = buf + 4352;
    #pragma unroll
    for (int r = 0; r < 4; r++) {
        int idx = r * 256 + tid;
        int kk = idx >> 4, uu = idx & 15;
        cp16(aS + kk * 68 + uu * 4, s_ahT + (kc + kk) * BB + uu * 4);
    }
    #pragma unroll
    for (int r = 0; r < 4; r++) {
        int idx = r * 256 + tid;
        int nn = idx >> 4, uu = idx & 15;
        cp16(wS + nn * 68 + uu * 4, pw + (size_t)(n0 + nn) * AA + kc + uu * 4);
    }
}

__device__ __forceinline__ void s2_compute(const float* buf, int mg, int ng,
                                           float acc[4][4])
{
    const float* aS = buf;
    const float* wS = buf + 4352;
    #pragma unroll
    for (int kq = 0; kq < 16; kq++) {
        float4 aa[4], ww[4];
        #pragma unroll
        for (int kk = 0; kk < 4; kk++)
            aa[kk] = *(const float4*)(aS + (kq * 4 + kk) * 68 + 4 * mg);
        #pragma unroll
        for (int q = 0; q < 4; q++)
            ww[q] = *(const float4*)(wS + (4 * ng + q) * 68 + kq * 4);
        #pragma unroll
        for (int q = 0; q < 4; q++) {
            float4 w = ww[q];
            acc[0][q] = fmaf(aa[0].x, w.x, acc[0][q]);
            acc[0][q] = fmaf(aa[1].x, w.y, acc[0][q]);
            acc[0][q] = fmaf(aa[2].x, w.z, acc[0][q]);
            acc[0][q] = fmaf(aa[3].x, w.w, acc[0][q]);
            acc[1][q] = fmaf(aa[0].y, w.x, acc[1][q]);
            acc[1][q] = fmaf(aa[1].y, w.y, acc[1][q]);
            acc[1][q] = fmaf(aa[2].y, w.z, acc[1][q]);
            acc[1][q] = fmaf(aa[3].y, w.w, acc[1][q]);
            acc[2][q] = fmaf(aa[0].z, w.x, acc[2][q]);
            acc[2][q] = fmaf(aa[1].z, w.y, acc[2][q]);
            acc[2][q] = fmaf(aa[2].z, w.z, acc[2][q]);
            acc[2][q] = fmaf(aa[3].z, w.w, acc[2][q]);
            acc[3][q] = fmaf(aa[0].w, w.x, acc[3][q]);
            acc[3][q] = fmaf(aa[1].w, w.y, acc[3][q]);
            acc[3][q] = fmaf(aa[2].w, w.z, acc[3][q]);
            acc[3][q] = fmaf(aa[3].w, w.w, acc[3][q]);
        }
    }
}

__device__ __forceinline__ void stage2(
    int l, int p, const float* __restrict__ xc,
    const float* __restrict__ pw, const float* __restrict__ pb,
    const float* __restrict__ fb, float* sm)
{
    const int b = blockIdx.x;
    if (b >= 224) return;
    const int tid = threadIdx.x;
    const int n0 = b * 64;
    const int mg = tid & 15, ng = tid >> 4;
    const float* fhOld = s_fh[p][l];

    float acc[4][4];
    #pragma unroll
    for (int r = 0; r < 4; r++)
        #pragma unroll
        for (int q = 0; q < 4; q++) acc[r][q] = 0.f;

    s2_fill(0, sm, n0, pw);        cp_commit();
    s2_fill(64, sm + 8704, n0, pw); cp_commit();
    cp_wait1();
    __syncthreads();
    s2_compute(sm, mg, ng, acc);
    cp_wait0();
    __syncthreads();
    s2_compute(sm + 8704, mg, ng, acc);

    const int seg = n0 >> 10;
    const int nb  = n0 + 4 * ng;
    #pragma unroll
    for (int r = 0; r < 4; r++) {
        int m = 4 * mg + r;
        #pragma unroll
        for (int q = 0; q < 4; q++) {
            int col = nb + q;
            float v = acc[r][q] + pb[col];
            if (seg == 0)
                s_xp[m * DD + col] = v * xc[m * DD + col];
            else if (seg == 1)
                s_hp[m * DD + (col - DD)] = v * fhOld[m * DD + (col - DD)];
            else if (seg < 6)
                s_p2[m * NG4 + (col - 2 * DD)] = v;
            else if (seg < 10)
                s_p3[m * NG4 + (col - 6 * DD)] = v;
            else
                s_b4[m * NG4 + (col - 10 * DD)] = v * fb[col - 10 * DD];
        }
    }
}

// ============================ stage 3a ======================================
// 256 CTAs = 2 ph x 32 N-tiles(128) x 4 K-chunks(256). 8 sub-chunks of 32 k,
// cp.async double-buffered. a m-major [mi][kk] stride 36, w n-major [nn][kk]
// stride 36. Thread tile 4m x 8n.
__device__ __forceinline__ void s3_fill(
    int s, float* buf, int kb, int n0,
    const float* __restrict__ src, const float* __restrict__ W)
{
    const int tid = threadIdx.x;
    const int k0 = kb + s * 32;
    float* aS = buf;
    float* wS = buf + 2304;
    #pragma unroll
    for (int r = 0; r < 2; r++) {
        int idx = r * 256 + tid;
        int mi = idx >> 3, uu = idx & 7;
        cp16(aS + mi * 36 + uu * 4, src + mi * DD + k0 + uu * 4);
    }
    #pragma unroll
    for (int r = 0; r < 4; r++) {
        int idx = r * 256 + tid;
        int nn = idx >> 3, uu = idx & 7;
        cp16(wS + nn * 36 + uu * 4, W + (size_t)(n0 + nn) * DD + k0 + uu * 4);
    }
}

__device__ __forceinline__ void stage3_gemm(
    const float* __restrict__ fwih, const float* __restrict__ fwhh, float* sm)
{
    const int tid = threadIdx.x, b = blockIdx.x;
    const int ph = b >> 7;
    const int nt = (b & 127) >> 2;
    const int kc = b & 3;
    const int n0 = nt * 128;
    const int kb = kc * 256;

    const float* src = ph ? s_hp : s_xp;
    const float* W   = ph ? fwhh : fwih;

    const int mg = tid & 15, ng = tid >> 4;

    float acc[4][8];
    #pragma unroll
    for (int r = 0; r < 4; r++)
        #pragma unroll
        for (int q = 0; q < 8; q++) acc[r][q] = 0.f;

    s3_fill(0, sm, kb, n0, src, W);
    cp_commit();

    for (int s = 0; s < 8; s++) {
        float* buf = sm + (s & 1) * 6912;
        if (s < 7) {
            s3_fill(s + 1, sm + ((s + 1) & 1) * 6912, kb, n0, src, W);
            cp_commit();
            cp_wait1();
        } else {
            cp_wait0();
        }
        __syncthreads();
        const float* aS = buf;
        const float* wS = buf + 2304;
        #pragma unroll
        for (int kq = 0; kq < 8; kq++) {
            float4 a4[4], w4[8];
            #pragma unroll
            for (int r = 0; r < 4; r++)
                a4[r] = *(const float4*)(aS + (4 * mg + r) * 36 + kq * 4);
            #pragma unroll
            for (int q = 0; q < 8; q++)
                w4[q] = *(const float4*)(wS + (8 * ng + q) * 36 + kq * 4);
            #pragma unroll
            for (int r = 0; r < 4; r++) {
                #pragma unroll
                for (int q = 0; q < 8; q++) {
                    acc[r][q] = fmaf(a4[r].x, w4[q].x, acc[r][q]);
                    acc[r][q] = fmaf(a4[r].y, w4[q].y, acc[r][q]);
                    acc[r][q] = fmaf(a4[r].z, w4[q].z, acc[r][q]);
                    acc[r][q] = fmaf(a4[r].w, w4[q].w, acc[r][q]);
                }
            }
        }
        __syncthreads();
    }

    float* dst = &s_pt[ph][kc][0][0];
    #pragma unroll
    for (int r = 0; r < 4; r++) {
        int m = 4 * mg + r;
        float4 o1, o2;
        o1.x = acc[r][0]; o1.y = acc[r][1]; o1.z = acc[r][2]; o1.w = acc[r][3];
        o2.x = acc[r][4]; o2.y = acc[r][5]; o2.z = acc[r][6]; o2.w = acc[r][7];
        *(float4*)(dst + (size_t)m * NG4 + n0 + 8 * ng)     = o1;
        *(float4*)(dst + (size_t)m * NG4 + n0 + 8 * ng + 4) = o2;
    }
}

// ============================ stage 3b ======================================
__device__ __forceinline__ void stage3b(
    int l, int p, int t, float* __restrict__ out)
{
    const int tid = threadIdx.x, b = blockIdx.x;
    const int m = tid >> 2, col = b * 4 + (tid & 3);

    float G[4];
    #pragma unroll
    for (int g = 0; g < 4; g++) {
        size_t cg = (size_t)m * NG4 + g * DD + col;
        float ig = s_pt[0][0][0][cg] + s_pt[0][1][0][cg]
                 + s_pt[0][2][0][cg] + s_pt[0][3][0][cg];
        float hg = s_pt[1][0][0][cg] + s_pt[1][1][0][cg]
                 + s_pt[1][2][0][cg] + s_pt[1][3][0][cg];
        G[g] = fmaf(ig, s_p2[cg], s_b4[cg]) + hg * s_p3[cg];
    }
    float cO = s_fc[l][m * DD + col];
    float cN = sigf(G[1]) * cO + sigf(G[0]) * tanhf(G[2]);
    float h  = sigf(G[3]) * tanhf(cN);
    s_fc[l][m * DD + col] = cN;
    s_fh[p ^ 1][l][m * DD + col] = h;
    if (l == 1) out[((size_t)t * BB + m) * DD + col] = h;
}

// ---------------- persistent kernel ----------------------------------------
__global__ void __launch_bounds__(NTHR, 2) alstm_persistent(Params P)
{
    extern __shared__ __align__(16) float sm[];
    const int tid = threadIdx.x, b = blockIdx.x;

    {   // zero recurrent state each replay
        int gtid = b * NTHR + tid, gsz = NCTA * NTHR;
        float* z1 = &s_ah[0][0][0];
        for (int i = gtid; i < 2 * NL * BB * AA; i += gsz) z1[i] = 0.f;
        float* z2 = &s_ac[0][0];
        for (int i = gtid; i < NL * BB * AA; i += gsz) z2[i] = 0.f;
        float* z3 = &s_fh[0][0][0];
        for (int i = gtid; i < 2 * NL * BB * DD; i += gsz) z3[i] = 0.f;
        float* z4 = &s_fc[0][0];
        for (int i = gtid; i < NL * BB * DD; i += gsz) z4[i] = 0.f;
    }
    grid_sync();

    for (int t = 0; t < TT; t++) {
        const int p = t & 1;
        const float* xt = P.x + (size_t)t * BB * DD;
        #pragma unroll
        for (int l = 0; l < NL; l++) {
            stage1(l, p, xt, P.awih[l], P.awhh[l], P.abih[l], P.abhh[l], sm);
            grid_sync();
            const float* xc = (l == 0) ? xt : s_fh[p ^ 1][0];
            stage2(l, p, xc, P.pw[l], P.pb[l], P.fb[l], sm);
            grid_sync();
            stage3_gemm(P.fwih[l], P.fwhh[l], sm);
            grid_sync();
            stage3b(l, p, t, P.out);
            grid_sync();
        }
    }
}

// ---------------- host launch ----------------------------------------------
extern "C" void kernel_launch(void* const* d_in, const int* in_sizes, int n_in,
                              void* d_out, int out_size)
{
    Params P;
    P.x       = (const float*)d_in[0];
    P.awih[0] = (const float*)d_in[1];  P.awih[1] = (const float*)d_in[10];
    P.awhh[0] = (const float*)d_in[2];  P.awhh[1] = (const float*)d_in[11];
    P.abih[0] = (const float*)d_in[3];  P.abih[1] = (const float*)d_in[12];
    P.abhh[0] = (const float*)d_in[4];  P.abhh[1] = (const float*)d_in[13];
    P.pw[0]   = (const float*)d_in[5];  P.pw[1]   = (const float*)d_in[14];
    P.pb[0]   = (const float*)d_in[6];  P.pb[1]   = (const float*)d_in[15];
    P.fwih[0] = (const float*)d_in[7];  P.fwih[1] = (const float*)d_in[16];
    P.fwhh[0] = (const float*)d_in[8];  P.fwhh[1] = (const float*)d_in[17];
    P.fb[0]   = (const float*)d_in[9];  P.fb[1]   = (const float*)d_in[18];
    P.out     = (float*)d_out;

    cudaFuncSetAttribute(alstm_persistent,
                         cudaFuncAttributeMaxDynamicSharedMemorySize,
                         SMEM_BYTES);
    alstm_persistent<<<NCTA, NTHR, SMEM_BYTES>>>(P);
}

// round 9
// speedup vs baseline: 3.6818x; 1.5130x over previous
#include <cuda_runtime.h>
#include <cuda_bf16.h>
#include <math.h>

#define TT    512
#define BB    64
#define DD    1024
#define AA    128
#define AIN   2176           // D + D + A
#define KHALF 1152           // KTOT/2
#define NL    2
#define NCTA  256
#define NTHR  256
#define NG4   4096           // 4 gates * D
#define SMEM_FLOATS 17408
#define SMEM_BYTES  (SMEM_FLOATS * 4)

// ---------------- persistent state ----------------------------------------
__device__ float s_ah[2][NL][BB * AA];
__device__ float s_ahT[AA * BB];
__device__ float s_ac[NL][BB * AA];
__device__ float s_fh[2][NL][BB * DD];
__device__ float s_fc[NL][BB * DD];
__device__ float s_p2[BB * NG4];
__device__ float s_p3[BB * NG4];
__device__ float s_b4[BB * NG4];
__device__ float s_pt[2][4][BB][NG4];     // K-split GEMM partials

// bf16 split activations (stage2 epilogue -> stage3)
__device__ __align__(16) __nv_bfloat16 g_xph[BB * DD];
__device__ __align__(16) __nv_bfloat16 g_xpl[BB * DD];
__device__ __align__(16) __nv_bfloat16 g_hph[BB * DD];
__device__ __align__(16) __nv_bfloat16 g_hpl[BB * DD];
// bf16 split weights [layer][ph: 0=fwih 1=fwhh]
__device__ __align__(16) __nv_bfloat16 g_wh[2][2][NG4 * DD];
__device__ __align__(16) __nv_bfloat16 g_wl[2][2][NG4 * DD];

// ---------------- cp.async helpers ------------------------------------------
__device__ __forceinline__ void cp16(void* dst, const void* src) {
    unsigned d = (unsigned)__cvta_generic_to_shared(dst);
    asm volatile("cp.async.cg.shared.global [%0], [%1], 16;" :: "r"(d), "l"(src));
}
__device__ __forceinline__ void cp_commit() {
    asm volatile("cp.async.commit_group;" ::: "memory");
}
__device__ __forceinline__ void cp_wait0() {
    asm volatile("cp.async.wait_group 0;" ::: "memory");
}
__device__ __forceinline__ void cp_wait1() {
    asm volatile("cp.async.wait_group 1;" ::: "memory");
}

// ---------------- mma / ldmatrix helpers -------------------------------------
__device__ __forceinline__ void ldsm4(unsigned r[4], unsigned addr) {
    asm volatile("ldmatrix.sync.aligned.m8n8.x4.shared.b16 {%0,%1,%2,%3}, [%4];"
                 : "=r"(r[0]), "=r"(r[1]), "=r"(r[2]), "=r"(r[3]) : "r"(addr));
}
__device__ __forceinline__ void mma16816(float d[4], const unsigned a[4],
                                         unsigned b0, unsigned b1) {
    asm volatile(
        "mma.sync.aligned.m16n8k16.row.col.f32.bf16.bf16.f32 "
        "{%0,%1,%2,%3},{%4,%5,%6,%7},{%8,%9},{%0,%1,%2,%3};"
        : "+f"(d[0]), "+f"(d[1]), "+f"(d[2]), "+f"(d[3])
        : "r"(a[0]), "r"(a[1]), "r"(a[2]), "r"(a[3]), "r"(b0), "r"(b1));
}

// ---------------- software grid barrier ------------------------------------
__device__ unsigned g_cnt = 0;
__device__ volatile unsigned g_gen = 0;

__device__ __forceinline__ void grid_sync() {
    __threadfence();
    __syncthreads();
    if (threadIdx.x == 0) {
        unsigned gen = g_gen;
        if (atomicAdd(&g_cnt, 1u) == NCTA - 1) {
            g_cnt = 0;
            __threadfence();
            g_gen = gen + 1;
        } else {
            while (g_gen == gen) { __nanosleep(64); }
        }
        __threadfence();
    }
    __syncthreads();
}

__device__ __forceinline__ float sigf(float x) { return 1.0f / (1.0f + expf(-x)); }

struct Params {
    const float* x;
    const float* awih[2]; const float* awhh[2];
    const float* abih[2]; const float* abhh[2];
    const float* pw[2];   const float* pb[2];
    const float* fwih[2]; const float* fwhh[2]; const float* fb[2];
    float* out;
};

// ============================ stage 1 (unchanged) ============================
__device__ __forceinline__ void s1_fill(
    int ci, float* buf, int mh, int j,
    const float* __restrict__ xc, const float* __restrict__ fhOld,
    const float* __restrict__ ahOth, const float* __restrict__ ahSelf,
    const float* __restrict__ awih, const float* __restrict__ awhh)
{
    const int tid = threadIdx.x;
    #pragma unroll
    for (int r = 0; r < 4; r++) {
        int idx = r * 256 + tid;
        int bf = idx >> 9, rem = idx & 511;
        int mi = rem >> 4, uu = rem & 15;
        int k = bf * KHALF + ci * 64 + uu * 4;
        int row = mh * 32 + mi;
        const float* src;
        if (k < DD)            src = xc + row * DD + k;
        else if (k < 2 * DD)   src = fhOld + row * DD + (k - DD);
        else if (k < AIN)      src = ahOth + row * AA + (k - 2 * DD);
        else                   src = ahSelf + row * AA + (k - AIN);
        cp16(buf + bf * 2176 + mi * 68 + uu * 4, src);
    }
    if (tid < 128) {
        int bf = tid >> 6, rem = tid & 63;
        int cc = rem >> 4, uu = rem & 15;
        int k = bf * KHALF + ci * 64 + uu * 4;
        int n = cc * AA + j;
        const float* src = (k < AIN) ? awih + (size_t)n * AIN + k
                                     : awhh + n * AA + (k - AIN);
        cp16(buf + 4352 + bf * 272 + cc * 68 + uu * 4, src);
    }
}

__device__ __forceinline__ void stage1(
    int l, int p, const float* __restrict__ xt,
    const float* __restrict__ awih, const float* __restrict__ awhh,
    const float* __restrict__ abih, const float* __restrict__ abhh,
    float* sm)
{
    const int tid = threadIdx.x, b = blockIdx.x;
    const int j = b & 127, mh = b >> 7;
    const int kh = tid >> 7, item = tid & 127;
    const int m = item >> 2, c = item & 3;
    float* red = sm + 9792;

    const float* xc     = (l == 0) ? xt : s_fh[p ^ 1][0];
    const float* fhOld  = s_fh[p][l];
    const float* ahSelf = s_ah[p][l];
    const float* ahOth  = (l == 0) ? s_ah[p][1] : s_ah[p ^ 1][0];

    float acc0 = 0.f, acc1 = 0.f;

    s1_fill(0, sm, mh, j, xc, fhOld, ahOth, ahSelf, awih, awhh);
    cp_commit();

    for (int ci = 0; ci < 18; ci++) {
        float* buf = sm + (ci & 1) * 4896;
        if (ci < 17) {
            s1_fill(ci + 1, sm + ((ci + 1) & 1) * 4896, mh, j,
                    xc, fhOld, ahOth, ahSelf, awih, awhh);
            cp_commit();
            cp_wait1();
        } else {
            cp_wait0();
        }
        __syncthreads();
        const float4* av = (const float4*)(buf + kh * 2176 + m * 68);
        const float4* wv = (const float4*)(buf + 4352 + kh * 272 + c * 68);
        #pragma unroll
        for (int q = 0; q < 16; q++) {
            float4 a4 = av[q], w4 = wv[q];
            acc0 = fmaf(a4.x, w4.x, acc0);
            acc1 = fmaf(a4.y, w4.y, acc1);
            acc0 = fmaf(a4.z, w4.z, acc0);
            acc1 = fmaf(a4.w, w4.w, acc1);
        }
        __syncthreads();
    }

    float g = acc0 + acc1;
    if (kh == 1) red[item] = g;
    __syncthreads();
    if (kh == 0) {
        g += red[item] + abih[c * AA + j] + abhh[c * AA + j];
        const unsigned F = 0xffffffffu;
        int base = (tid & 31) & ~3;
        float gi = __shfl_sync(F, g, base + 0);
        float gf = __shfl_sync(F, g, base + 1);
        float gz = __shfl_sync(F, g, base + 2);
        float go = __shfl_sync(F, g, base + 3);
        if (c == 0) {
            int row = mh * 32 + m;
            float cO = s_ac[l][row * AA + j];
            float cN = sigf(gf) * cO + sigf(gi) * tanhf(gz);
            float h  = sigf(go) * tanhf(cN);
            s_ac[l][row * AA + j] = cN;
            s_ah[p ^ 1][l][row * AA + j] = h;
            s_ahT[j * BB + row] = h;
        }
    }
    __syncthreads();
}

// ============================ stage 2 ========================================
__device__ __forceinline__ void s2_fill(
    int kc, float* buf, int n0, const float* __restrict__ pw)
{
    const int tid = threadIdx.x;
    float* aS = buf;
    float* wS = buf + 4352;
    #pragma unroll
    for (int r = 0; r < 4; r++) {
        int idx = r * 256 + tid;
        int kk = idx >> 4, uu = idx & 15;
        cp16(aS + kk * 68 + uu * 4, s_ahT + (kc + kk) * BB + uu * 4);
    }
    #pragma unroll
    for (int r = 0; r < 4; r++) {
        int idx = r * 256 + tid;
        int nn = idx >> 4, uu = idx & 15;
        cp16(wS + nn * 68 + uu * 4, pw + (size_t)(n0 + nn) * AA + kc + uu * 4);
    }
}

__device__ __forceinline__ void s2_compute(const float* buf, int mg, int ng,
                                           float acc[4][4])
{
    const float* aS = buf;
    const float* wS = buf + 4352;
    #pragma unroll
    for (int kq = 0; kq < 16; kq++) {
        float4 aa[4], ww[4];
        #pragma unroll
        for (int kk = 0; kk < 4; kk++)
            aa[kk] = *(const float4*)(aS + (kq * 4 + kk) * 68 + 4 * mg);
        #pragma unroll
        for (int q = 0; q < 4; q++)
            ww[q] = *(const float4*)(wS + (4 * ng + q) * 68 + kq * 4);
        #pragma unroll
        for (int q = 0; q < 4; q++) {
            float4 w = ww[q];
            acc[0][q] = fmaf(aa[0].x, w.x, acc[0][q]);
            acc[0][q] = fmaf(aa[1].x, w.y, acc[0][q]);
            acc[0][q] = fmaf(aa[2].x, w.z, acc[0][q]);
            acc[0][q] = fmaf(aa[3].x, w.w, acc[0][q]);
            acc[1][q] = fmaf(aa[0].y, w.x, acc[1][q]);
            acc[1][q] = fmaf(aa[1].y, w.y, acc[1][q]);
            acc[1][q] = fmaf(aa[2].y, w.z, acc[1][q]);
            acc[1][q] = fmaf(aa[3].y, w.w, acc[1][q]);
            acc[2][q] = fmaf(aa[0].z, w.x, acc[2][q]);
            acc[2][q] = fmaf(aa[1].z, w.y, acc[2][q]);
            acc[2][q] = fmaf(aa[2].z, w.z, acc[2][q]);
            acc[2][q] = fmaf(aa[3].z, w.w, acc[2][q]);
            acc[3][q] = fmaf(aa[0].w, w.x, acc[3][q]);
            acc[3][q] = fmaf(aa[1].w, w.y, acc[3][q]);
            acc[3][q] = fmaf(aa[2].w, w.z, acc[3][q]);
            acc[3][q] = fmaf(aa[3].w, w.w, acc[3][q]);
        }
    }
}

__device__ __forceinline__ void stage2(
    int l, int p, const float* __restrict__ xc,
    const float* __restrict__ pw, const float* __restrict__ pb,
    const float* __restrict__ fb, float* sm)
{
    const int b = blockIdx.x;
    if (b >= 224) return;
    const int tid = threadIdx.x;
    const int n0 = b * 64;
    const int mg = tid & 15, ng = tid >> 4;
    const float* fhOld = s_fh[p][l];

    float acc[4][4];
    #pragma unroll
    for (int r = 0; r < 4; r++)
        #pragma unroll
        for (int q = 0; q < 4; q++) acc[r][q] = 0.f;

    s2_fill(0, sm, n0, pw);         cp_commit();
    s2_fill(64, sm + 8704, n0, pw); cp_commit();
    cp_wait1();
    __syncthreads();
    s2_compute(sm, mg, ng, acc);
    cp_wait0();
    __syncthreads();
    s2_compute(sm + 8704, mg, ng, acc);

    const int seg = n0 >> 10;
    const int nb  = n0 + 4 * ng;
    #pragma unroll
    for (int r = 0; r < 4; r++) {
        int m = 4 * mg + r;
        #pragma unroll
        for (int q = 0; q < 4; q++) {
            int col = nb + q;
            float v = acc[r][q] + pb[col];
            if (seg == 0) {
                float xv = v * xc[m * DD + col];
                __nv_bfloat16 h = __float2bfloat16(xv);
                g_xph[m * DD + col] = h;
                g_xpl[m * DD + col] = __float2bfloat16(xv - __bfloat162float(h));
            } else if (seg == 1) {
                int cc = col - DD;
                float hv = v * fhOld[m * DD + cc];
                __nv_bfloat16 h = __float2bfloat16(hv);
                g_hph[m * DD + cc] = h;
                g_hpl[m * DD + cc] = __float2bfloat16(hv - __bfloat162float(h));
            } else if (seg < 6)
                s_p2[m * NG4 + (col - 2 * DD)] = v;
            else if (seg < 10)
                s_p3[m * NG4 + (col - 6 * DD)] = v;
            else
                s_b4[m * NG4 + (col - 10 * DD)] = v * fb[col - 10 * DD];
        }
    }
}

// ============================ stage 3a: tensor-core bf16x3 ===================
// 256 CTAs = 2 ph x 32 N-tiles(128) x 4 K-chunks(256).
// smem/buffer (halves): A_hi[64][40] @0, A_lo @2560, W_hi[128][40] @5120,
// W_lo @10240; buffer = 15360 halves (30720 B), x2 buffers.
__device__ __forceinline__ void s3_fill(
    int s, __nv_bfloat16* buf, int kb, int n0,
    const __nv_bfloat16* __restrict__ Ah, const __nv_bfloat16* __restrict__ Al,
    const __nv_bfloat16* __restrict__ Wh, const __nv_bfloat16* __restrict__ Wl)
{
    const int tid = threadIdx.x;
    const int k0 = kb + s * 32;
    #pragma unroll
    for (int r = 0; r < 2; r++) {        // A hi/lo: 512 cp16
        int idx = r * 256 + tid;
        int part = idx >> 8, m = (idx >> 2) & 63, u = idx & 3;
        const __nv_bfloat16* src = (part ? Al : Ah) + m * DD + k0 + u * 8;
        cp16(buf + part * 2560 + m * 40 + u * 8, src);
    }
    #pragma unroll
    for (int r = 0; r < 4; r++) {        // W hi/lo: 1024 cp16
        int idx = r * 256 + tid;
        int part = idx >> 9, n = (idx >> 2) & 127, u = idx & 3;
        const __nv_bfloat16* src = (part ? Wl : Wh) + (size_t)(n0 + n) * DD + k0 + u * 8;
        cp16(buf + 5120 + part * 5120 + n * 40 + u * 8, src);
    }
}

__device__ __forceinline__ void stage3_gemm(int l, float* smf)
{
    __nv_bfloat16* sm = (__nv_bfloat16*)smf;
    const int tid = threadIdx.x, b = blockIdx.x;
    const int ph = b >> 7;
    const int nt = (b & 127) >> 2;
    const int kc = b & 3;
    const int n0 = nt * 128;
    const int kb = kc * 256;

    const __nv_bfloat16* Ah = ph ? g_hph : g_xph;
    const __nv_bfloat16* Al = ph ? g_hpl : g_xpl;
    const __nv_bfloat16* Wh = g_wh[l][ph];
    const __nv_bfloat16* Wl = g_wl[l][ph];

    const int w = tid >> 5, lane = tid & 31;
    const int wm = w & 1, wn = w >> 1;        // 2 m-groups x 4 n-groups
    const int g = lane >> 2, t4 = lane & 3;

    // ldmatrix per-lane offsets (halves)
    const int tA = lane >> 3;
    const int aoff = ((tA & 1) * 8 + (lane & 7)) * 40 + (tA >> 1) * 8;
    const int boff = ((lane >> 4) * 8 + (lane & 7)) * 40 + ((lane >> 3) & 1) * 8;

    const unsigned smemBase = (unsigned)__cvta_generic_to_shared(sm);

    float D[2][4][4];
    #pragma unroll
    for (int im = 0; im < 2; im++)
        #pragma unroll
        for (int q = 0; q < 4; q++) {
            D[im][q][0] = 0.f; D[im][q][1] = 0.f;
            D[im][q][2] = 0.f; D[im][q][3] = 0.f;
        }

    s3_fill(0, sm, kb, n0, Ah, Al, Wh, Wl);
    cp_commit();

    for (int s = 0; s < 8; s++) {
        if (s < 7) {
            s3_fill(s + 1, sm + ((s + 1) & 1) * 15360, kb, n0, Ah, Al, Wh, Wl);
            cp_commit();
            cp_wait1();
        } else {
            cp_wait0();
        }
        __syncthreads();
        const unsigned bufBase = smemBase + (unsigned)((s & 1) * 15360 * 2);
        #pragma unroll
        for (int ks = 0; ks < 2; ks++) {
            const unsigned kadd = ks * 16;
            unsigned ah[2][4], al[2][4];
            #pragma unroll
            for (int im = 0; im < 2; im++) {
                unsigned base = bufBase +
                    2u * ((wm * 32 + im * 16) * 40 + kadd + aoff);
                ldsm4(ah[im], base);
                ldsm4(al[im], base + 2u * 2560);
            }
            unsigned bh[2][4], bl[2][4];
            #pragma unroll
            for (int in2 = 0; in2 < 2; in2++) {
                unsigned base = bufBase +
                    2u * (5120 + (wn * 32 + in2 * 16) * 40 + kadd + boff);
                ldsm4(bh[in2], base);
                ldsm4(bl[in2], base + 2u * 5120);
            }
            #pragma unroll
            for (int im = 0; im < 2; im++) {
                #pragma unroll
                for (int in8 = 0; in8 < 4; in8++) {
                    int in2 = in8 >> 1, o = (in8 & 1) * 2;
                    mma16816(D[im][in8], ah[im], bh[in2][o], bh[in2][o + 1]);
                    mma16816(D[im][in8], ah[im], bl[in2][o], bl[in2][o + 1]);
                    mma16816(D[im][in8], al[im], bh[in2][o], bh[in2][o + 1]);
                }
            }
        }
        __syncthreads();
    }

    float* dst = &s_pt[ph][kc][0][0];
    #pragma unroll
    for (int im = 0; im < 2; im++) {
        int m0 = wm * 32 + im * 16 + g;
        #pragma unroll
        for (int in8 = 0; in8 < 4; in8++) {
            int col = n0 + wn * 32 + in8 * 8 + 2 * t4;
            *(float2*)(dst + (size_t)m0 * NG4 + col) =
                make_float2(D[im][in8][0], D[im][in8][1]);
            *(float2*)(dst + (size_t)(m0 + 8) * NG4 + col) =
                make_float2(D[im][in8][2], D[im][in8][3]);
        }
    }
}

// ============================ stage 3b =======================================
__device__ __forceinline__ void stage3b(
    int l, int p, int t, float* __restrict__ out)
{
    const int tid = threadIdx.x, b = blockIdx.x;
    const int m = tid >> 2, col = b * 4 + (tid & 3);

    float G[4];
    #pragma unroll
    for (int g = 0; g < 4; g++) {
        size_t cg = (size_t)m * NG4 + g * DD + col;
        float ig = s_pt[0][0][0][cg] + s_pt[0][1][0][cg]
                 + s_pt[0][2][0][cg] + s_pt[0][3][0][cg];
        float hg = s_pt[1][0][0][cg] + s_pt[1][1][0][cg]
                 + s_pt[1][2][0][cg] + s_pt[1][3][0][cg];
        G[g] = fmaf(ig, s_p2[cg], s_b4[cg]) + hg * s_p3[cg];
    }
    float cO = s_fc[l][m * DD + col];
    float cN = sigf(G[1]) * cO + sigf(G[0]) * tanhf(G[2]);
    float h  = sigf(G[3]) * tanhf(cN);
    s_fc[l][m * DD + col] = cN;
    s_fh[p ^ 1][l][m * DD + col] = h;
    if (l == 1) out[((size_t)t * BB + m) * DD + col] = h;
}

// ---------------- persistent kernel ----------------------------------------
__global__ void __launch_bounds__(NTHR, 2) alstm_persistent(Params P)
{
    extern __shared__ __align__(16) float sm[];
    const int tid = threadIdx.x, b = blockIdx.x;
    const int gtid = b * NTHR + tid, gsz = NCTA * NTHR;

    {   // zero recurrent state each replay
        float* z1 = &s_ah[0][0][0];
        for (int i = gtid; i < 2 * NL * BB * AA; i += gsz) z1[i] = 0.f;
        float* z2 = &s_ac[0][0];
        for (int i = gtid; i < NL * BB * AA; i += gsz) z2[i] = 0.f;
        float* z3 = &s_fh[0][0][0];
        for (int i = gtid; i < 2 * NL * BB * DD; i += gsz) z3[i] = 0.f;
        float* z4 = &s_fc[0][0];
        for (int i = gtid; i < NL * BB * DD; i += gsz) z4[i] = 0.f;
    }

    {   // split fast-LSTM weights into bf16 hi/lo (every replay, deterministic)
        const float* Wsrc[4] = {P.fwih[0], P.fwhh[0], P.fwih[1], P.fwhh[1]};
        #pragma unroll
        for (int mtx = 0; mtx < 4; mtx++) {
            const float4* s4 = (const float4*)Wsrc[mtx];
            __nv_bfloat162* dh = (__nv_bfloat162*)&g_wh[mtx >> 1][mtx & 1][0];
            __nv_bfloat162* dl = (__nv_bfloat162*)&g_wl[mtx >> 1][mtx & 1][0];
            for (int i = gtid; i < NG4 * DD / 4; i += gsz) {
                float4 v = s4[i];
                float f[4] = {v.x, v.y, v.z, v.w};
                __nv_bfloat16 hh[4], ll[4];
                #pragma unroll
                for (int q = 0; q < 4; q++) {
                    hh[q] = __float2bfloat16(f[q]);
                    ll[q] = __float2bfloat16(f[q] - __bfloat162float(hh[q]));
                }
                __nv_bfloat162 a, c, e, d2;
                a.x = hh[0]; a.y = hh[1];
                c.x = hh[2]; c.y = hh[3];
                e.x = ll[0]; e.y = ll[1];
                d2.x = ll[2]; d2.y = ll[3];
                dh[2 * i] = a; dh[2 * i + 1] = c;
                dl[2 * i] = e; dl[2 * i + 1] = d2;
            }
        }
    }
    grid_sync();

    for (int t = 0; t < TT; t++) {
        const int p = t & 1;
        const float* xt = P.x + (size_t)t * BB * DD;
        #pragma unroll
        for (int l = 0; l < NL; l++) {
            stage1(l, p, xt, P.awih[l], P.awhh[l], P.abih[l], P.abhh[l], sm);
            grid_sync();
            const float* xc = (l == 0) ? xt : s_fh[p ^ 1][0];
            stage2(l, p, xc, P.pw[l], P.pb[l], P.fb[l], sm);
            grid_sync();
            stage3_gemm(l, sm);
            grid_sync();
            stage3b(l, p, t, P.out);
            grid_sync();
        }
    }
}

// ---------------- host launch ----------------------------------------------
extern "C" void kernel_launch(void* const* d_in, const int* in_sizes, int n_in,
                              void* d_out, int out_size)
{
    Params P;
    P.x       = (const float*)d_in[0];
    P.awih[0] = (const float*)d_in[1];  P.awih[1] = (const float*)d_in[10];
    P.awhh[0] = (const float*)d_in[2];  P.awhh[1] = (const float*)d_in[11];
    P.abih[0] = (const float*)d_in[3];  P.abih[1] = (const float*)d_in[12];
    P.abhh[0] = (const float*)d_in[4];  P.abhh[1] = (const float*)d_in[13];
    P.pw[0]   = (const float*)d_in[5];  P.pw[1]   = (const float*)d_in[14];
    P.pb[0]   = (const float*)d_in[6];  P.pb[1]   = (const float*)d_in[15];
    P.fwih[0] = (const float*)d_in[7];  P.fwih[1] = (const float*)d_in[16];
    P.fwhh[0] = (const float*)d_in[8];  P.fwhh[1] = (const float*)d_in[17];
    P.fb[0]   = (const float*)d_in[9];  P.fb[1]   = (const float*)d_in[18];
    P.out     = (float*)d_out;

    cudaFuncSetAttribute(alstm_persistent,
                         cudaFuncAttributeMaxDynamicSharedMemorySize,
                         SMEM_BYTES);
    alstm_persistent<<<NCTA, NTHR, SMEM_BYTES>>>(P);
}

// round 10
// speedup vs baseline: 6.0853x; 1.6528x over previous
#include <cuda_runtime.h>
#include <cuda_bf16.h>
#include <math.h>

#define TT    512
#define BB    64
#define DD    1024
#define AA    128
#define AIN   2176           // D + D + A
#define KT1   2304           // composite K for stage1
#define NL    2
#define NCTA  256
#define NTHR  256
#define NG4   4096           // 4 gates * D
#define S1KC  16             // stage1 K-splits (144 k each)
#define SMEM_BYTES 69632

// ---------------- fp32 persistent state -------------------------------------
__device__ float s_ac[NL][BB * AA];
__device__ float s_fh[2][NL][BB * DD];
__device__ float s_fc[NL][BB * DD];
__device__ float s_p2[BB * NG4];
__device__ float s_p3[BB * NG4];
__device__ float s_b4[BB * NG4];
__device__ float s_pt[2][4][BB][NG4];        // stage3 K-split partials
__device__ float s_pt1[S1KC][BB][512];       // stage1 K-split partials

// ---------------- bf16 split state / operands -------------------------------
__device__ __align__(16) __nv_bfloat16 g_ahh[2][NL][BB * AA];
__device__ __align__(16) __nv_bfloat16 g_ahl[2][NL][BB * AA];
__device__ __align__(16) __nv_bfloat16 g_fhh[2][NL][BB * DD];
__device__ __align__(16) __nv_bfloat16 g_fhl[2][NL][BB * DD];
__device__ __align__(16) __nv_bfloat16 g_xph[BB * DD];
__device__ __align__(16) __nv_bfloat16 g_xpl[BB * DD];
__device__ __align__(16) __nv_bfloat16 g_hph[BB * DD];
__device__ __align__(16) __nv_bfloat16 g_hpl[BB * DD];
// pre-split inputs/weights (built once per replay)
__device__ __align__(16) __nv_bfloat16 g_xh[TT * BB * DD];
__device__ __align__(16) __nv_bfloat16 g_xl[TT * BB * DD];
__device__ __align__(16) __nv_bfloat16 g_w1h[2][512 * KT1];   // stage1 composite W
__device__ __align__(16) __nv_bfloat16 g_w1l[2][512 * KT1];
__device__ __align__(16) __nv_bfloat16 g_pwh[2][14336 * 128];
__device__ __align__(16) __nv_bfloat16 g_pwl[2][14336 * 128];
__device__ __align__(16) __nv_bfloat16 g_wh[2][2][NG4 * DD];  // stage3 W
__device__ __align__(16) __nv_bfloat16 g_wl[2][2][NG4 * DD];

// ---------------- cp.async / mma helpers -------------------------------------
__device__ __forceinline__ void cp16(void* dst, const void* src) {
    unsigned d = (unsigned)__cvta_generic_to_shared(dst);
    asm volatile("cp.async.cg.shared.global [%0], [%1], 16;" :: "r"(d), "l"(src));
}
__device__ __forceinline__ void cp_commit() {
    asm volatile("cp.async.commit_group;" ::: "memory");
}
__device__ __forceinline__ void cp_wait0() {
    asm volatile("cp.async.wait_group 0;" ::: "memory");
}
__device__ __forceinline__ void cp_wait1() {
    asm volatile("cp.async.wait_group 1;" ::: "memory");
}
__device__ __forceinline__ void ldsm4(unsigned r[4], unsigned addr) {
    asm volatile("ldmatrix.sync.aligned.m8n8.x4.shared.b16 {%0,%1,%2,%3}, [%4];"
                 : "=r"(r[0]), "=r"(r[1]), "=r"(r[2]), "=r"(r[3]) : "r"(addr));
}
__device__ __forceinline__ void mma16816(float d[4], const unsigned a[4],
                                         unsigned b0, unsigned b1) {
    asm volatile(
        "mma.sync.aligned.m16n8k16.row.col.f32.bf16.bf16.f32 "
        "{%0,%1,%2,%3},{%4,%5,%6,%7},{%8,%9},{%0,%1,%2,%3};"
        : "+f"(d[0]), "+f"(d[1]), "+f"(d[2]), "+f"(d[3])
        : "r"(a[0]), "r"(a[1]), "r"(a[2]), "r"(a[3]), "r"(b0), "r"(b1));
}
// bf16x3: D += Ah*Bh + Ah*Bl + Al*Bh
__device__ __forceinline__ void mma_x3(float d[4], const unsigned ah[4],
                                       const unsigned al[4],
                                       unsigned bh0, unsigned bh1,
                                       unsigned bl0, unsigned bl1) {
    mma16816(d, ah, bh0, bh1);
    mma16816(d, ah, bl0, bl1);
    mma16816(d, al, bh0, bh1);
}

// ---------------- software grid barrier ------------------------------------
__device__ unsigned g_cnt = 0;
__device__ volatile unsigned g_gen = 0;

__device__ __forceinline__ void grid_sync() {
    __threadfence();
    __syncthreads();
    if (threadIdx.x == 0) {
        unsigned gen = g_gen;
        if (atomicAdd(&g_cnt, 1u) == NCTA - 1) {
            g_cnt = 0;
            __threadfence();
            g_gen = gen + 1;
        } else {
            while (g_gen == gen) { __nanosleep(32); }
        }
        __threadfence();
    }
    __syncthreads();
}

__device__ __forceinline__ float sigf(float x) { return 1.0f / (1.0f + expf(-x)); }
__device__ __forceinline__ void bsplit(float v, __nv_bfloat16* ph, __nv_bfloat16* pl) {
    __nv_bfloat16 h = __float2bfloat16(v);
    *ph = h;
    *pl = __float2bfloat16(v - __bfloat162float(h));
}

struct Params {
    const float* x;
    const float* awih[2]; const float* awhh[2];
    const float* abih[2]; const float* abhh[2];
    const float* pw[2];   const float* pb[2];
    const float* fwih[2]; const float* fwhh[2]; const float* fb[2];
    float* out;
};

// ============================ stage 1 GEMM (tensor) ==========================
// 128 CTAs = 8 n-tiles(64 gate cols) x 16 k-splits(144).
// smem buffer (halves): A_hi[64][56]@0, A_lo@3584, W_hi[64][56]@7168, W_lo@10752
// buffer = 14336 halves; x2 buffers. Chunks of 48 k (3 k16 each), 3 chunks.
__device__ __forceinline__ void s1_fill(
    int ch, __nv_bfloat16* buf, int kc, int n0,
    const __nv_bfloat16* __restrict__ xh, const __nv_bfloat16* __restrict__ xl,
    const __nv_bfloat16* __restrict__ fhh, const __nv_bfloat16* __restrict__ fhl,
    const __nv_bfloat16* __restrict__ aoh, const __nv_bfloat16* __restrict__ aol,
    const __nv_bfloat16* __restrict__ ash, const __nv_bfloat16* __restrict__ asl,
    const __nv_bfloat16* __restrict__ wh, const __nv_bfloat16* __restrict__ wl)
{
    const int tid = threadIdx.x;
    const int k0 = kc * 144 + ch * 48;
    #pragma unroll
    for (int r = 0; r < 3; r++) {            // A: 768 cp16
        int idx = r * 256 + tid;
        int part = idx >= 384 ? 1 : 0;
        int rem = idx - part * 384;
        int m = rem / 6, u = rem - m * 6;
        int k = k0 + u * 8;
        const __nv_bfloat16* s;
        if (k < DD)            s = (part ? xl : xh) + m * DD + k;
        else if (k < 2 * DD)   s = (part ? fhl : fhh) + m * DD + (k - DD);
        else if (k < AIN)      s = (part ? aol : aoh) + m * AA + (k - 2 * DD);
        else                   s = (part ? asl : ash) + m * AA + (k - AIN);
        cp16(buf + part * 3584 + m * 56 + u * 8, s);
    }
    #pragma unroll
    for (int r = 0; r < 3; r++) {            // W: 768 cp16
        int idx = r * 256 + tid;
        int part = idx >= 384 ? 1 : 0;
        int rem = idx - part * 384;
        int n = rem / 6, u = rem - n * 6;
        cp16(buf + 7168 + part * 3584 + n * 56 + u * 8,
             (part ? wl : wh) + (size_t)(n0 + n) * KT1 + k0 + u * 8);
    }
}

__device__ __forceinline__ void stage1_gemm(
    int l, int p, int t, __nv_bfloat16* sm,
    const __nv_bfloat16* xh, const __nv_bfloat16* xl)
{
    const int tid = threadIdx.x, b = blockIdx.x;
    if (b >= 128) return;
    const int nt = b >> 4, kc = b & 15;
    const int n0 = nt * 64;

    const __nv_bfloat16* fhh = g_fhh[p][l];
    const __nv_bfloat16* fhl = g_fhl[p][l];
    const __nv_bfloat16* aoh = (l == 0) ? g_ahh[p][1] : g_ahh[p ^ 1][0];
    const __nv_bfloat16* aol = (l == 0) ? g_ahl[p][1] : g_ahl[p ^ 1][0];
    const __nv_bfloat16* ash = g_ahh[p][l];
    const __nv_bfloat16* asl = g_ahl[p][l];
    const __nv_bfloat16* wh = g_w1h[l];
    const __nv_bfloat16* wl = g_w1l[l];

    const int w = tid >> 5, lane = tid & 31;
    const int wm = w & 1, wn = w >> 1;       // 2m x 4n(16) groups
    const int g = lane >> 2, t4 = lane & 3;
    const int tA = lane >> 3;
    const int arow = (tA & 1) * 8 + (lane & 7), acol = (tA >> 1) * 8;
    const int brow = (lane >> 4) * 8 + (lane & 7), bcol = ((lane >> 3) & 1) * 8;
    const unsigned base0 = (unsigned)__cvta_generic_to_shared(sm);

    float D[2][2][4];
    #pragma unroll
    for (int im = 0; im < 2; im++)
        #pragma unroll
        for (int q = 0; q < 2; q++)
            D[im][q][0] = D[im][q][1] = D[im][q][2] = D[im][q][3] = 0.f;

    s1_fill(0, sm, kc, n0, xh, xl, fhh, fhl, aoh, aol, ash, asl, wh, wl);
    cp_commit();

    for (int ch = 0; ch < 3; ch++) {
        if (ch < 2) {
            s1_fill(ch + 1, sm + ((ch + 1) & 1) * 14336, kc, n0,
                    xh, xl, fhh, fhl, aoh, aol, ash, asl, wh, wl);
            cp_commit();
            cp_wait1();
        } else {
            cp_wait0();
        }
        __syncthreads();
        const unsigned bufB = base0 + (unsigned)((ch & 1) * 14336 * 2);
        #pragma unroll
        for (int ck = 0; ck < 3; ck++) {
            const int kadd = ck * 16;
            unsigned ah[2][4], al[2][4];
            #pragma unroll
            for (int im = 0; im < 2; im++) {
                unsigned a = bufB + 2u * ((wm * 32 + im * 16 + arow) * 56 + kadd + acol);
                ldsm4(ah[im], a);
                ldsm4(al[im], a + 2u * 3584);
            }
            unsigned bh[4], bl[4];
            {
                unsigned a = bufB + 2u * (7168 + (wn * 16 + brow) * 56 + kadd + bcol);
                ldsm4(bh, a);
                ldsm4(bl, a + 2u * 3584);
            }
            #pragma unroll
            for (int im = 0; im < 2; im++)
                #pragma unroll
                for (int q = 0; q < 2; q++)
                    mma_x3(D[im][q], ah[im], al[im],
                           bh[q * 2], bh[q * 2 + 1], bl[q * 2], bl[q * 2 + 1]);
        }
        __syncthreads();
    }

    #pragma unroll
    for (int im = 0; im < 2; im++) {
        int m0 = wm * 32 + im * 16 + g;
        #pragma unroll
        for (int q = 0; q < 2; q++) {
            int col = n0 + wn * 16 + q * 8 + 2 * t4;
            *(float2*)&s_pt1[kc][m0][col]     = make_float2(D[im][q][0], D[im][q][1]);
            *(float2*)&s_pt1[kc][m0 + 8][col] = make_float2(D[im][q][2], D[im][q][3]);
        }
    }
}

// ============================ stage 1 pointwise ==============================
// 32 CTAs x 256: one thread per (m, j) cell; reduces 16 partials x 4 gates.
__device__ __forceinline__ void s1_point(
    int l, int p,
    const float* __restrict__ abih, const float* __restrict__ abhh)
{
    const int b = blockIdx.x;
    if (b >= 32) return;
    const int idx = b * 256 + threadIdx.x;
    const int m = idx >> 7, j = idx & 127;

    float gt[4];
    #pragma unroll
    for (int c = 0; c < 4; c++) {
        int n = c * AA + j;
        float s = 0.f;
        #pragma unroll
        for (int kc = 0; kc < S1KC; kc++) s += s_pt1[kc][m][n];
        gt[c] = s + abih[n] + abhh[n];
    }
    float cO = s_ac[l][m * AA + j];
    float cN = sigf(gt[1]) * cO + sigf(gt[0]) * tanhf(gt[2]);
    float h  = sigf(gt[3]) * tanhf(cN);
    s_ac[l][m * AA + j] = cN;
    bsplit(h, &g_ahh[p ^ 1][l][m * AA + j], &g_ahl[p ^ 1][l][m * AA + j]);
}

// ============================ stage 2 (tensor) ===============================
// 224 CTAs x 64 n. A = ah_new bf16 [64][128], W = pw bf16. K=128 one pass.
// smem halves: A_hi[64][136]@0, A_lo@8704, W_hi@17408, W_lo@26112.
__device__ __forceinline__ void s2_store(
    int seg, int m, int col, float v,
    const float* __restrict__ xc, const float* __restrict__ fhOld,
    const float* __restrict__ fb)
{
    if (seg == 0) {
        float xv = v * xc[m * DD + col];
        bsplit(xv, &g_xph[m * DD + col], &g_xpl[m * DD + col]);
    } else if (seg == 1) {
        int cc = col - DD;
        float hv = v * fhOld[m * DD + cc];
        bsplit(hv, &g_hph[m * DD + cc], &g_hpl[m * DD + cc]);
    } else if (seg < 6)
        s_p2[m * NG4 + (col - 2 * DD)] = v;
    else if (seg < 10)
        s_p3[m * NG4 + (col - 6 * DD)] = v;
    else
        s_b4[m * NG4 + (col - 10 * DD)] = v * fb[col - 10 * DD];
}

__device__ __forceinline__ void stage2(
    int l, int p, const float* __restrict__ xc,
    const float* __restrict__ pb, const float* __restrict__ fb,
    __nv_bfloat16* sm)
{
    const int tid = threadIdx.x, b = blockIdx.x;
    if (b >= 224) return;
    const int n0 = b * 64;
    const float* fhOld = s_fh[p][l];
    const __nv_bfloat16* ahh = g_ahh[p ^ 1][l];
    const __nv_bfloat16* ahl = g_ahl[p ^ 1][l];
    const __nv_bfloat16* pwh = g_pwh[l];
    const __nv_bfloat16* pwl = g_pwl[l];

    #pragma unroll
    for (int r = 0; r < 8; r++) {            // A: 2048 cp16
        int idx = r * 256 + tid;
        int part = idx >> 10, rem = idx & 1023;
        int m = rem >> 4, u = rem & 15;
        cp16(sm + part * 8704 + m * 136 + u * 8,
             (part ? ahl : ahh) + m * 128 + u * 8);
    }
    #pragma unroll
    for (int r = 0; r < 8; r++) {            // W: 2048 cp16
        int idx = r * 256 + tid;
        int part = idx >> 10, rem = idx & 1023;
        int n = rem >> 4, u = rem & 15;
        cp16(sm + 17408 + part * 8704 + n * 136 + u * 8,
             (part ? pwl : pwh) + (size_t)(n0 + n) * 128 + u * 8);
    }
    cp_commit();

    const int w = tid >> 5, lane = tid & 31;
    const int wm = w & 1, wn = w >> 1;
    const int g = lane >> 2, t4 = lane & 3;
    const int tA = lane >> 3;
    const int arow = (tA & 1) * 8 + (lane & 7), acol = (tA >> 1) * 8;
    const int brow = (lane >> 4) * 8 + (lane & 7), bcol = ((lane >> 3) & 1) * 8;
    const unsigned base0 = (unsigned)__cvta_generic_to_shared(sm);

    float D[2][2][4];
    #pragma unroll
    for (int im = 0; im < 2; im++)
        #pragma unroll
        for (int q = 0; q < 2; q++)
            D[im][q][0] = D[im][q][1] = D[im][q][2] = D[im][q][3] = 0.f;

    cp_wait0();
    __syncthreads();

    #pragma unroll
    for (int k16 = 0; k16 < 8; k16++) {
        const int kadd = k16 * 16;
        unsigned ah[2][4], al[2][4];
        #pragma unroll
        for (int im = 0; im < 2; im++) {
            unsigned a = base0 + 2u * ((wm * 32 + im * 16 + arow) * 136 + kadd + acol);
            ldsm4(ah[im], a);
            ldsm4(al[im], a + 2u * 8704);
        }
        unsigned bh[4], bl[4];
        {
            unsigned a = base0 + 2u * (17408 + (wn * 16 + brow) * 136 + kadd + bcol);
            ldsm4(bh, a);
            ldsm4(bl, a + 2u * 8704);
        }
        #pragma unroll
        for (int im = 0; im < 2; im++)
            #pragma unroll
            for (int q = 0; q < 2; q++)
                mma_x3(D[im][q], ah[im], al[im],
                       bh[q * 2], bh[q * 2 + 1], bl[q * 2], bl[q * 2 + 1]);
    }
    __syncthreads();

    const int seg = n0 >> 10;
    #pragma unroll
    for (int im = 0; im < 2; im++) {
        int m0 = wm * 32 + im * 16 + g;
        #pragma unroll
        for (int q = 0; q < 2; q++) {
            int col = n0 + wn * 16 + q * 8 + 2 * t4;
            s2_store(seg, m0, col,     D[im][q][0] + pb[col],     xc, fhOld, fb);
            s2_store(seg, m0, col + 1, D[im][q][1] + pb[col + 1], xc, fhOld, fb);
            s2_store(seg, m0 + 8, col,     D[im][q][2] + pb[col],     xc, fhOld, fb);
            s2_store(seg, m0 + 8, col + 1, D[im][q][3] + pb[col + 1], xc, fhOld, fb);
        }
    }
}

// ============================ stage 3a (tensor, unchanged R8) ================
__device__ __forceinline__ void s3_fill(
    int s, __nv_bfloat16* buf, int kb, int n0,
    const __nv_bfloat16* __restrict__ Ah, const __nv_bfloat16* __restrict__ Al,
    const __nv_bfloat16* __restrict__ Wh, const __nv_bfloat16* __restrict__ Wl)
{
    const int tid = threadIdx.x;
    const int k0 = kb + s * 32;
    #pragma unroll
    for (int r = 0; r < 2; r++) {
        int idx = r * 256 + tid;
        int part = idx >> 8, m = (idx >> 2) & 63, u = idx & 3;
        cp16(buf + part * 2560 + m * 40 + u * 8,
             (part ? Al : Ah) + m * DD + k0 + u * 8);
    }
    #pragma unroll
    for (int r = 0; r < 4; r++) {
        int idx = r * 256 + tid;
        int part = idx >> 9, n = (idx >> 2) & 127, u = idx & 3;
        cp16(buf + 5120 + part * 5120 + n * 40 + u * 8,
             (part ? Wl : Wh) + (size_t)(n0 + n) * DD + k0 + u * 8);
    }
}

__device__ __forceinline__ void stage3_gemm(int l, __nv_bfloat16* sm)
{
    const int tid = threadIdx.x, b = blockIdx.x;
    const int ph = b >> 7;
    const int nt = (b & 127) >> 2;
    const int kc = b & 3;
    const int n0 = nt * 128;
    const int kb = kc * 256;

    const __nv_bfloat16* Ah = ph ? g_hph : g_xph;
    const __nv_bfloat16* Al = ph ? g_hpl : g_xpl;
    const __nv_bfloat16* Wh = g_wh[l][ph];
    const __nv_bfloat16* Wl = g_wl[l][ph];

    const int w = tid >> 5, lane = tid & 31;
    const int wm = w & 1, wn = w >> 1;
    const int g = lane >> 2, t4 = lane & 3;
    const int tA = lane >> 3;
    const int aoff = ((tA & 1) * 8 + (lane & 7)) * 40 + (tA >> 1) * 8;
    const int boff = ((lane >> 4) * 8 + (lane & 7)) * 40 + ((lane >> 3) & 1) * 8;
    const unsigned smemBase = (unsigned)__cvta_generic_to_shared(sm);

    float D[2][4][4];
    #pragma unroll
    for (int im = 0; im < 2; im++)
        #pragma unroll
        for (int q = 0; q < 4; q++)
            D[im][q][0] = D[im][q][1] = D[im][q][2] = D[im][q][3] = 0.f;

    s3_fill(0, sm, kb, n0, Ah, Al, Wh, Wl);
    cp_commit();

    for (int s = 0; s < 8; s++) {
        if (s < 7) {
            s3_fill(s + 1, sm + ((s + 1) & 1) * 15360, kb, n0, Ah, Al, Wh, Wl);
            cp_commit();
            cp_wait1();
        } else {
            cp_wait0();
        }
        __syncthreads();
        const unsigned bufBase = smemBase + (unsigned)((s & 1) * 15360 * 2);
        #pragma unroll
        for (int ks = 0; ks < 2; ks++) {
            const unsigned kadd = ks * 16;
            unsigned ah[2][4], al[2][4];
            #pragma unroll
            for (int im = 0; im < 2; im++) {
                unsigned base = bufBase + 2u * ((wm * 32 + im * 16) * 40 + kadd + aoff);
                ldsm4(ah[im], base);
                ldsm4(al[im], base + 2u * 2560);
            }
            unsigned bh[2][4], bl[2][4];
            #pragma unroll
            for (int in2 = 0; in2 < 2; in2++) {
                unsigned base = bufBase + 2u * (5120 + (wn * 32 + in2 * 16) * 40 + kadd + boff);
                ldsm4(bh[in2], base);
                ldsm4(bl[in2], base + 2u * 5120);
            }
            #pragma unroll
            for (int im = 0; im < 2; im++)
                #pragma unroll
                for (int in8 = 0; in8 < 4; in8++) {
                    int in2 = in8 >> 1, o = (in8 & 1) * 2;
                    mma_x3(D[im][in8], ah[im], al[im],
                           bh[in2][o], bh[in2][o + 1], bl[in2][o], bl[in2][o + 1]);
                }
        }
        __syncthreads();
    }

    float* dst = &s_pt[ph][kc][0][0];
    #pragma unroll
    for (int im = 0; im < 2; im++) {
        int m0 = wm * 32 + im * 16 + g;
        #pragma unroll
        for (int in8 = 0; in8 < 4; in8++) {
            int col = n0 + wn * 32 + in8 * 8 + 2 * t4;
            *(float2*)(dst + (size_t)m0 * NG4 + col) =
                make_float2(D[im][in8][0], D[im][in8][1]);
            *(float2*)(dst + (size_t)(m0 + 8) * NG4 + col) =
                make_float2(D[im][in8][2], D[im][in8][3]);
        }
    }
}

// ============================ stage 3b =======================================
__device__ __forceinline__ void stage3b(
    int l, int p, int t, float* __restrict__ out)
{
    const int tid = threadIdx.x, b = blockIdx.x;
    const int m = tid >> 2, col = b * 4 + (tid & 3);

    float G[4];
    #pragma unroll
    for (int g = 0; g < 4; g++) {
        size_t cg = (size_t)m * NG4 + g * DD + col;
        float ig = s_pt[0][0][0][cg] + s_pt[0][1][0][cg]
                 + s_pt[0][2][0][cg] + s_pt[0][3][0][cg];
        float hg = s_pt[1][0][0][cg] + s_pt[1][1][0][cg]
                 + s_pt[1][2][0][cg] + s_pt[1][3][0][cg];
        G[g] = fmaf(ig, s_p2[cg], s_b4[cg]) + hg * s_p3[cg];
    }
    float cO = s_fc[l][m * DD + col];
    float cN = sigf(G[1]) * cO + sigf(G[0]) * tanhf(G[2]);
    float h  = sigf(G[3]) * tanhf(cN);
    s_fc[l][m * DD + col] = cN;
    s_fh[p ^ 1][l][m * DD + col] = h;
    bsplit(h, &g_fhh[p ^ 1][l][m * DD + col], &g_fhl[p ^ 1][l][m * DD + col]);
    if (l == 1) out[((size_t)t * BB + m) * DD + col] = h;
}

// ---------------- persistent kernel ----------------------------------------
__global__ void __launch_bounds__(NTHR, 2) alstm_persistent(Params P)
{
    extern __shared__ __align__(16) float smf[];
    __nv_bfloat16* sm = (__nv_bfloat16*)smf;
    const int tid = threadIdx.x, b = blockIdx.x;
    const int gtid = b * NTHR + tid, gsz = NCTA * NTHR;

    {   // zero recurrent state each replay
        float* z2 = &s_ac[0][0];
        for (int i = gtid; i < NL * BB * AA; i += gsz) z2[i] = 0.f;
        float* z3 = &s_fh[0][0][0];
        for (int i = gtid; i < 2 * NL * BB * DD; i += gsz) z3[i] = 0.f;
        float* z4 = &s_fc[0][0];
        for (int i = gtid; i < NL * BB * DD; i += gsz) z4[i] = 0.f;
        __nv_bfloat16* z5 = &g_ahh[0][0][0];
        __nv_bfloat16* z6 = &g_ahl[0][0][0];
        for (int i = gtid; i < 2 * NL * BB * AA; i += gsz) { z5[i] = __nv_bfloat16(0.f); z6[i] = __nv_bfloat16(0.f); }
        __nv_bfloat16* z7 = &g_fhh[0][0][0];
        __nv_bfloat16* z8 = &g_fhl[0][0][0];
        for (int i = gtid; i < 2 * NL * BB * DD; i += gsz) { z7[i] = __nv_bfloat16(0.f); z8[i] = __nv_bfloat16(0.f); }
    }

    {   // split x (whole sequence)
        const float4* s4 = (const float4*)P.x;
        for (int i = gtid; i < TT * BB * DD / 4; i += gsz) {
            float4 v = s4[i];
            float f[4] = {v.x, v.y, v.z, v.w};
            #pragma unroll
            for (int q = 0; q < 4; q++)
                bsplit(f[q], &g_xh[4 * i + q], &g_xl[4 * i + q]);
        }
    }
    {   // split stage3 weights
        const float* Wsrc[4] = {P.fwih[0], P.fwhh[0], P.fwih[1], P.fwhh[1]};
        #pragma unroll
        for (int mtx = 0; mtx < 4; mtx++) {
            const float4* s4 = (const float4*)Wsrc[mtx];
            __nv_bfloat16* dh = &g_wh[mtx >> 1][mtx & 1][0];
            __nv_bfloat16* dl = &g_wl[mtx >> 1][mtx & 1][0];
            for (int i = gtid; i < NG4 * DD / 4; i += gsz) {
                float4 v = s4[i];
                float f[4] = {v.x, v.y, v.z, v.w};
                #pragma unroll
                for (int q = 0; q < 4; q++)
                    bsplit(f[q], &dh[4 * i + q], &dl[4 * i + q]);
            }
        }
    }
    {   // split pw
        #pragma unroll
        for (int l = 0; l < 2; l++) {
            const float4* s4 = (const float4*)P.pw[l];
            for (int i = gtid; i < 14336 * 128 / 4; i += gsz) {
                float4 v = s4[i];
                float f[4] = {v.x, v.y, v.z, v.w};
                #pragma unroll
                for (int q = 0; q < 4; q++)
                    bsplit(f[q], &g_pwh[l][4 * i + q], &g_pwl[l][4 * i + q]);
            }
        }
    }
    {   // build composite stage1 weights (gather awih|awhh along K, then split)
        #pragma unroll
        for (int l = 0; l < 2; l++) {
            const float* wih = P.awih[l];
            const float* whh = P.awhh[l];
            for (int i = gtid; i < 512 * KT1; i += gsz) {
                int n = i / KT1, k = i - n * KT1;
                float v = (k < AIN) ? wih[(size_t)n * AIN + k]
                                    : whh[n * AA + (k - AIN)];
                bsplit(v, &g_w1h[l][i], &g_w1l[l][i]);
            }
        }
    }
    grid_sync();

    for (int t = 0; t < TT; t++) {
        const int p = t & 1;
        #pragma unroll
        for (int l = 0; l < NL; l++) {
            const __nv_bfloat16* xh = (l == 0) ? g_xh + (size_t)t * BB * DD
                                               : g_fhh[p ^ 1][0];
            const __nv_bfloat16* xl = (l == 0) ? g_xl + (size_t)t * BB * DD
                                               : g_fhl[p ^ 1][0];
            stage1_gemm(l, p, t, sm, xh, xl);
            grid_sync();
            s1_point(l, p, P.abih[l], P.abhh[l]);
            grid_sync();
            const float* xc = (l == 0) ? P.x + (size_t)t * BB * DD
                                       : s_fh[p ^ 1][0];
            stage2(l, p, xc, P.pb[l], P.fb[l], sm);
            grid_sync();
            stage3_gemm(l, sm);
            grid_sync();
            stage3b(l, p, t, P.out);
            grid_sync();
        }
    }
}

// ---------------- host launch ----------------------------------------------
extern "C" void kernel_launch(void* const* d_in, const int* in_sizes, int n_in,
                              void* d_out, int out_size)
{
    Params P;
    P.x       = (const float*)d_in[0];
    P.awih[0] = (const float*)d_in[1];  P.awih[1] = (const float*)d_in[10];
    P.awhh[0] = (const float*)d_in[2];  P.awhh[1] = (const float*)d_in[11];
    P.abih[0] = (const float*)d_in[3];  P.abih[1] = (const float*)d_in[12];
    P.abhh[0] = (const float*)d_in[4];  P.abhh[1] = (const float*)d_in[13];
    P.pw[0]   = (const float*)d_in[5];  P.pw[1]   = (const float*)d_in[14];
    P.pb[0]   = (const float*)d_in[6];  P.pb[1]   = (const float*)d_in[15];
    P.fwih[0] = (const float*)d_in[7];  P.fwih[1] = (const float*)d_in[16];
    P.fwhh[0] = (const float*)d_in[8];  P.fwhh[1] = (const float*)d_in[17];
    P.fb[0]   = (const float*)d_in[9];  P.fb[1]   = (const float*)d_in[18];
    P.out     = (float*)d_out;

    cudaFuncSetAttribute(alstm_persistent,
                         cudaFuncAttributeMaxDynamicSharedMemorySize,
                         SMEM_BYTES);
    alstm_persistent<<<NCTA, NTHR, SMEM_BYTES>>>(P);
}

// round 11
// speedup vs baseline: 6.7862x; 1.1152x over previous
#include <cuda_runtime.h>
#include <cuda_bf16.h>
#include <math.h>

#define TT    512
#define BB    64
#define DD    1024
#define AA    128
#define AIN   2176           // D + D + A
#define KT1   2304           // composite K for stage1
#define NL    2
#define NCTA  256
#define NTHR  256
#define NG4   4096           // 4 gates * D
#define S1KC  16             // stage1 K-splits (144 k each)
#define SMEM_BYTES 69632

// ---------------- fp32 persistent state -------------------------------------
__device__ float s_ac[NL][BB * AA];
__device__ float s_fh[2][NL][BB * DD];
__device__ float s_fc[NL][BB * DD];
__device__ float s_p2[BB * NG4];
__device__ float s_p3[BB * NG4];
__device__ float s_b4[BB * NG4];
__device__ float s_pt[2][4][BB][NG4];        // stage3 K-split partials
__device__ float s_pt1[S1KC][BB][512];       // stage1 K-split partials

// ---------------- bf16 split state / operands -------------------------------
__device__ __align__(16) __nv_bfloat16 g_ahh[2][NL][BB * AA];
__device__ __align__(16) __nv_bfloat16 g_ahl[2][NL][BB * AA];
__device__ __align__(16) __nv_bfloat16 g_fhh[2][NL][BB * DD];
__device__ __align__(16) __nv_bfloat16 g_fhl[2][NL][BB * DD];
__device__ __align__(16) __nv_bfloat16 g_xph[BB * DD];
__device__ __align__(16) __nv_bfloat16 g_xpl[BB * DD];
__device__ __align__(16) __nv_bfloat16 g_hph[BB * DD];
__device__ __align__(16) __nv_bfloat16 g_hpl[BB * DD];
// pre-split inputs/weights (built once per replay)
__device__ __align__(16) __nv_bfloat16 g_xh[TT * BB * DD];
__device__ __align__(16) __nv_bfloat16 g_xl[TT * BB * DD];
__device__ __align__(16) __nv_bfloat16 g_w1h[2][512 * KT1];
__device__ __align__(16) __nv_bfloat16 g_w1l[2][512 * KT1];
__device__ __align__(16) __nv_bfloat16 g_pwh[2][14336 * 128];
__device__ __align__(16) __nv_bfloat16 g_pwl[2][14336 * 128];
__device__ __align__(16) __nv_bfloat16 g_wh[2][2][NG4 * DD];
__device__ __align__(16) __nv_bfloat16 g_wl[2][2][NG4 * DD];

// ---------------- cp.async / mma helpers -------------------------------------
// .cg (L2 path) for MUTABLE data — always fresh, no L1 staleness concerns.
__device__ __forceinline__ void cp16(void* dst, const void* src) {
    unsigned d = (unsigned)__cvta_generic_to_shared(dst);
    asm volatile("cp.async.cg.shared.global [%0], [%1], 16;" :: "r"(d), "l"(src));
}
// .ca (L1-allocating) for IMMUTABLE weights — persists across steps.
__device__ __forceinline__ void cp16w(void* dst, const void* src) {
    unsigned d = (unsigned)__cvta_generic_to_shared(dst);
    asm volatile("cp.async.ca.shared.global [%0], [%1], 16;" :: "r"(d), "l"(src));
}
__device__ __forceinline__ void cp_commit() {
    asm volatile("cp.async.commit_group;" ::: "memory");
}
__device__ __forceinline__ void cp_wait0() {
    asm volatile("cp.async.wait_group 0;" ::: "memory");
}
__device__ __forceinline__ void cp_wait1() {
    asm volatile("cp.async.wait_group 1;" ::: "memory");
}
__device__ __forceinline__ void ldsm4(unsigned r[4], unsigned addr) {
    asm volatile("ldmatrix.sync.aligned.m8n8.x4.shared.b16 {%0,%1,%2,%3}, [%4];"
                 : "=r"(r[0]), "=r"(r[1]), "=r"(r[2]), "=r"(r[3]) : "r"(addr));
}
__device__ __forceinline__ void mma16816(float d[4], const unsigned a[4],
                                         unsigned b0, unsigned b1) {
    asm volatile(
        "mma.sync.aligned.m16n8k16.row.col.f32.bf16.bf16.f32 "
        "{%0,%1,%2,%3},{%4,%5,%6,%7},{%8,%9},{%0,%1,%2,%3};"
        : "+f"(d[0]), "+f"(d[1]), "+f"(d[2]), "+f"(d[3])
        : "r"(a[0]), "r"(a[1]), "r"(a[2]), "r"(a[3]), "r"(b0), "r"(b1));
}
__device__ __forceinline__ void mma_x3(float d[4], const unsigned ah[4],
                                       const unsigned al[4],
                                       unsigned bh0, unsigned bh1,
                                       unsigned bl0, unsigned bl1) {
    mma16816(d, ah, bh0, bh1);
    mma16816(d, ah, bl0, bl1);
    mma16816(d, al, bh0, bh1);
}

// ---------------- fence-free release/acquire grid barrier --------------------
__device__ unsigned g_cnt2;   // monotonic arrivals
__device__ unsigned g_gen2;   // monotonic generation

__device__ __forceinline__ void grid_sync(unsigned& gen) {
    __syncthreads();
    if (threadIdx.x == 0) {
        unsigned old;
        asm volatile("atom.add.acq_rel.gpu.global.u32 %0, [%1], 1;"
                     : "=r"(old) : "l"(&g_cnt2) : "memory");
        unsigned target = gen + 1;
        if ((old & (NCTA - 1u)) == NCTA - 1u) {
            asm volatile("st.release.gpu.global.u32 [%0], %1;"
                         :: "l"(&g_gen2), "r"(target) : "memory");
        } else {
            unsigned v;
            do {
                __nanosleep(32);
                asm volatile("ld.acquire.gpu.global.u32 %0, [%1];"
                             : "=r"(v) : "l"(&g_gen2) : "memory");
            } while ((int)(v - target) < 0);
        }
    }
    gen += 1;
    __syncthreads();
}

__device__ __forceinline__ float sigf(float x) { return 1.0f / (1.0f + expf(-x)); }
__device__ __forceinline__ void bsplit(float v, __nv_bfloat16* ph, __nv_bfloat16* pl) {
    __nv_bfloat16 h = __float2bfloat16(v);
    *ph = h;
    *pl = __float2bfloat16(v - __bfloat162float(h));
}

struct Params {
    const float* x;
    const float* awih[2]; const float* awhh[2];
    const float* abih[2]; const float* abhh[2];
    const float* pw[2];   const float* pb[2];
    const float* fwih[2]; const float* fwhh[2]; const float* fb[2];
    float* out;
};

// ============================ stage 1 GEMM (tensor) ==========================
// 128 CTAs = 8 n-tiles(64 gate cols) x 16 k-splits(144). Chunks of 48 k.
// smem/buffer (halves): A_hi[64][56]@0, A_lo@3584, W_hi[64][56]@7168, W_lo@10752.
__device__ __forceinline__ void s1_fillA(
    int ch, __nv_bfloat16* buf, int kc,
    const __nv_bfloat16* __restrict__ xh, const __nv_bfloat16* __restrict__ xl,
    const __nv_bfloat16* __restrict__ fhh, const __nv_bfloat16* __restrict__ fhl,
    const __nv_bfloat16* __restrict__ aoh, const __nv_bfloat16* __restrict__ aol,
    const __nv_bfloat16* __restrict__ ash, const __nv_bfloat16* __restrict__ asl)
{
    const int tid = threadIdx.x;
    const int k0 = kc * 144 + ch * 48;
    #pragma unroll
    for (int r = 0; r < 3; r++) {
        int idx = r * 256 + tid;
        int part = idx >= 384 ? 1 : 0;
        int rem = idx - part * 384;
        int m = rem / 6, u = rem - m * 6;
        int k = k0 + u * 8;
        const __nv_bfloat16* s;
        if (k < DD)            s = (part ? xl : xh) + m * DD + k;
        else if (k < 2 * DD)   s = (part ? fhl : fhh) + m * DD + (k - DD);
        else if (k < AIN)      s = (part ? aol : aoh) + m * AA + (k - 2 * DD);
        else                   s = (part ? asl : ash) + m * AA + (k - AIN);
        cp16(buf + part * 3584 + m * 56 + u * 8, s);
    }
}

__device__ __forceinline__ void s1_fillW(
    int ch, __nv_bfloat16* buf, int kc, int n0,
    const __nv_bfloat16* __restrict__ wh, const __nv_bfloat16* __restrict__ wl)
{
    const int tid = threadIdx.x;
    const int k0 = kc * 144 + ch * 48;
    #pragma unroll
    for (int r = 0; r < 3; r++) {
        int idx = r * 256 + tid;
        int part = idx >= 384 ? 1 : 0;
        int rem = idx - part * 384;
        int n = rem / 6, u = rem - n * 6;
        cp16w(buf + 7168 + part * 3584 + n * 56 + u * 8,
              (part ? wl : wh) + (size_t)(n0 + n) * KT1 + k0 + u * 8);
    }
}

// Prefetch W chunk 0 into buffer 0 (issued before the barrier preceding stage1).
__device__ __forceinline__ void s1_prefetchW(int l, __nv_bfloat16* sm)
{
    const int b = blockIdx.x;
    if (b >= 128) return;
    const int nt = b >> 4, kc = b & 15;
    s1_fillW(0, sm, kc, nt * 64, g_w1h[l], g_w1l[l]);
    cp_commit();
}

__device__ __forceinline__ void stage1_gemm(
    int l, int p, __nv_bfloat16* sm,
    const __nv_bfloat16* xh, const __nv_bfloat16* xl)
{
    const int tid = threadIdx.x, b = blockIdx.x;
    if (b >= 128) return;
    const int nt = b >> 4, kc = b & 15;
    const int n0 = nt * 64;

    const __nv_bfloat16* fhh = g_fhh[p][l];
    const __nv_bfloat16* fhl = g_fhl[p][l];
    const __nv_bfloat16* aoh = (l == 0) ? g_ahh[p][1] : g_ahh[p ^ 1][0];
    const __nv_bfloat16* aol = (l == 0) ? g_ahl[p][1] : g_ahl[p ^ 1][0];
    const __nv_bfloat16* ash = g_ahh[p][l];
    const __nv_bfloat16* asl = g_ahl[p][l];
    const __nv_bfloat16* wh = g_w1h[l];
    const __nv_bfloat16* wl = g_w1l[l];

    const int w = tid >> 5, lane = tid & 31;
    const int wm = w & 1, wn = w >> 1;
    const int g = lane >> 2, t4 = lane & 3;
    const int tA = lane >> 3;
    const int arow = (tA & 1) * 8 + (lane & 7), acol = (tA >> 1) * 8;
    const int brow = (lane >> 4) * 8 + (lane & 7), bcol = ((lane >> 3) & 1) * 8;
    const unsigned base0 = (unsigned)__cvta_generic_to_shared(sm);

    float D[2][2][4];
    #pragma unroll
    for (int im = 0; im < 2; im++)
        #pragma unroll
        for (int q = 0; q < 2; q++)
            D[im][q][0] = D[im][q][1] = D[im][q][2] = D[im][q][3] = 0.f;

    // W chunk 0 was prefetched before the preceding barrier; fill A only.
    s1_fillA(0, sm, kc, xh, xl, fhh, fhl, aoh, aol, ash, asl);
    cp_commit();

    for (int ch = 0; ch < 3; ch++) {
        if (ch < 2) {
            __nv_bfloat16* nb = sm + ((ch + 1) & 1) * 14336;
            s1_fillA(ch + 1, nb, kc, xh, xl, fhh, fhl, aoh, aol, ash, asl);
            s1_fillW(ch + 1, nb, kc, n0, wh, wl);
            cp_commit();
            cp_wait1();
        } else {
            cp_wait0();
        }
        __syncthreads();
        const unsigned bufB = base0 + (unsigned)((ch & 1) * 14336 * 2);
        #pragma unroll
        for (int ck = 0; ck < 3; ck++) {
            const int kadd = ck * 16;
            unsigned ah[2][4], al[2][4];
            #pragma unroll
            for (int im = 0; im < 2; im++) {
                unsigned a = bufB + 2u * ((wm * 32 + im * 16 + arow) * 56 + kadd + acol);
                ldsm4(ah[im], a);
                ldsm4(al[im], a + 2u * 3584);
            }
            unsigned bh[4], bl[4];
            {
                unsigned a = bufB + 2u * (7168 + (wn * 16 + brow) * 56 + kadd + bcol);
                ldsm4(bh, a);
                ldsm4(bl, a + 2u * 3584);
            }
            #pragma unroll
            for (int im = 0; im < 2; im++)
                #pragma unroll
                for (int q = 0; q < 2; q++)
                    mma_x3(D[im][q], ah[im], al[im],
                           bh[q * 2], bh[q * 2 + 1], bl[q * 2], bl[q * 2 + 1]);
        }
        __syncthreads();
    }

    #pragma unroll
    for (int im = 0; im < 2; im++) {
        int m0 = wm * 32 + im * 16 + g;
        #pragma unroll
        for (int q = 0; q < 2; q++) {
            int col = n0 + wn * 16 + q * 8 + 2 * t4;
            *(float2*)&s_pt1[kc][m0][col]     = make_float2(D[im][q][0], D[im][q][1]);
            *(float2*)&s_pt1[kc][m0 + 8][col] = make_float2(D[im][q][2], D[im][q][3]);
        }
    }
}

// ============================ stage 1 pointwise ==============================
__device__ __forceinline__ void s1_point(
    int l, int p,
    const float* __restrict__ abih, const float* __restrict__ abhh)
{
    const int b = blockIdx.x;
    if (b >= 32) return;
    const int idx = b * 256 + threadIdx.x;
    const int m = idx >> 7, j = idx & 127;

    float gt[4];
    #pragma unroll
    for (int c = 0; c < 4; c++) {
        int n = c * AA + j;
        float s = 0.f;
        #pragma unroll
        for (int kc = 0; kc < S1KC; kc++) s += __ldcg(&s_pt1[kc][m][n]);
        gt[c] = s + abih[n] + abhh[n];
    }
    float cO = __ldcg(&s_ac[l][m * AA + j]);
    float cN = sigf(gt[1]) * cO + sigf(gt[0]) * tanhf(gt[2]);
    float h  = sigf(gt[3]) * tanhf(cN);
    s_ac[l][m * AA + j] = cN;
    bsplit(h, &g_ahh[p ^ 1][l][m * AA + j], &g_ahl[p ^ 1][l][m * AA + j]);
}

// ============================ stage 2 (tensor) ===============================
// smem halves: A_hi[64][136]@0, A_lo@8704, W_hi@17408, W_lo@26112.
__device__ __forceinline__ void s2_prefetchW(int l, __nv_bfloat16* sm)
{
    const int tid = threadIdx.x, b = blockIdx.x;
    if (b >= 224) return;
    const int n0 = b * 64;
    const __nv_bfloat16* pwh = g_pwh[l];
    const __nv_bfloat16* pwl = g_pwl[l];
    #pragma unroll
    for (int r = 0; r < 8; r++) {
        int idx = r * 256 + tid;
        int part = idx >> 10, rem = idx & 1023;
        int n = rem >> 4, u = rem & 15;
        cp16w(sm + 17408 + part * 8704 + n * 136 + u * 8,
              (part ? pwl : pwh) + (size_t)(n0 + n) * 128 + u * 8);
    }
    cp_commit();
}

__device__ __forceinline__ void s2_store(
    int seg, int m, int col, float v,
    const float* __restrict__ xc, const float* __restrict__ fhOld,
    const float* __restrict__ fb)
{
    if (seg == 0) {
        float xv = v * __ldcg(xc + m * DD + col);
        bsplit(xv, &g_xph[m * DD + col], &g_xpl[m * DD + col]);
    } else if (seg == 1) {
        int cc = col - DD;
        float hv = v * __ldcg(fhOld + m * DD + cc);
        bsplit(hv, &g_hph[m * DD + cc], &g_hpl[m * DD + cc]);
    } else if (seg < 6)
        s_p2[m * NG4 + (col - 2 * DD)] = v;
    else if (seg < 10)
        s_p3[m * NG4 + (col - 6 * DD)] = v;
    else
        s_b4[m * NG4 + (col - 10 * DD)] = v * fb[col - 10 * DD];
}

__device__ __forceinline__ void stage2(
    int l, int p, const float* __restrict__ xc,
    const float* __restrict__ pb, const float* __restrict__ fb,
    __nv_bfloat16* sm)
{
    const int tid = threadIdx.x, b = blockIdx.x;
    if (b >= 224) return;
    const int n0 = b * 64;
    const float* fhOld = s_fh[p][l];
    const __nv_bfloat16* ahh = g_ahh[p ^ 1][l];
    const __nv_bfloat16* ahl = g_ahl[p ^ 1][l];

    #pragma unroll
    for (int r = 0; r < 8; r++) {            // A fill (W prefetched earlier)
        int idx = r * 256 + tid;
        int part = idx >> 10, rem = idx & 1023;
        int m = rem >> 4, u = rem & 15;
        cp16(sm + part * 8704 + m * 136 + u * 8,
             (part ? ahl : ahh) + m * 128 + u * 8);
    }
    cp_commit();

    const int w = tid >> 5, lane = tid & 31;
    const int wm = w & 1, wn = w >> 1;
    const int g = lane >> 2, t4 = lane & 3;
    const int tA = lane >> 3;
    const int arow = (tA & 1) * 8 + (lane & 7), acol = (tA >> 1) * 8;
    const int brow = (lane >> 4) * 8 + (lane & 7), bcol = ((lane >> 3) & 1) * 8;
    const unsigned base0 = (unsigned)__cvta_generic_to_shared(sm);

    float D[2][2][4];
    #pragma unroll
    for (int im = 0; im < 2; im++)
        #pragma unroll
        for (int q = 0; q < 2; q++)
            D[im][q][0] = D[im][q][1] = D[im][q][2] = D[im][q][3] = 0.f;

    cp_wait0();
    __syncthreads();

    #pragma unroll
    for (int k16 = 0; k16 < 8; k16++) {
        const int kadd = k16 * 16;
        unsigned ah[2][4], al[2][4];
        #pragma unroll
        for (int im = 0; im < 2; im++) {
            unsigned a = base0 + 2u * ((wm * 32 + im * 16 + arow) * 136 + kadd + acol);
            ldsm4(ah[im], a);
            ldsm4(al[im], a + 2u * 8704);
        }
        unsigned bh[4], bl[4];
        {
            unsigned a = base0 + 2u * (17408 + (wn * 16 + brow) * 136 + kadd + bcol);
            ldsm4(bh, a);
            ldsm4(bl, a + 2u * 8704);
        }
        #pragma unroll
        for (int im = 0; im < 2; im++)
            #pragma unroll
            for (int q = 0; q < 2; q++)
                mma_x3(D[im][q], ah[im], al[im],
                       bh[q * 2], bh[q * 2 + 1], bl[q * 2], bl[q * 2 + 1]);
    }
    __syncthreads();

    const int seg = n0 >> 10;
    #pragma unroll
    for (int im = 0; im < 2; im++) {
        int m0 = wm * 32 + im * 16 + g;
        #pragma unroll
        for (int q = 0; q < 2; q++) {
            int col = n0 + wn * 16 + q * 8 + 2 * t4;
            s2_store(seg, m0, col,     D[im][q][0] + pb[col],     xc, fhOld, fb);
            s2_store(seg, m0, col + 1, D[im][q][1] + pb[col + 1], xc, fhOld, fb);
            s2_store(seg, m0 + 8, col,     D[im][q][2] + pb[col],     xc, fhOld, fb);
            s2_store(seg, m0 + 8, col + 1, D[im][q][3] + pb[col + 1], xc, fhOld, fb);
        }
    }
}

// ============================ stage 3a (tensor) ==============================
// smem/buffer (halves): A_hi[64][40]@0, A_lo@2560, W_hi[128][40]@5120, W_lo@10240.
__device__ __forceinline__ void s3_fillA(
    int s, __nv_bfloat16* buf, int kb,
    const __nv_bfloat16* __restrict__ Ah, const __nv_bfloat16* __restrict__ Al)
{
    const int tid = threadIdx.x;
    const int k0 = kb + s * 32;
    #pragma unroll
    for (int r = 0; r < 2; r++) {
        int idx = r * 256 + tid;
        int part = idx >> 8, m = (idx >> 2) & 63, u = idx & 3;
        cp16(buf + part * 2560 + m * 40 + u * 8,
             (part ? Al : Ah) + m * DD + k0 + u * 8);
    }
}

__device__ __forceinline__ void s3_fillW(
    int s, __nv_bfloat16* buf, int kb, int n0,
    const __nv_bfloat16* __restrict__ Wh, const __nv_bfloat16* __restrict__ Wl)
{
    const int tid = threadIdx.x;
    const int k0 = kb + s * 32;
    #pragma unroll
    for (int r = 0; r < 4; r++) {
        int idx = r * 256 + tid;
        int part = idx >> 9, n = (idx >> 2) & 127, u = idx & 3;
        cp16w(buf + 5120 + part * 5120 + n * 40 + u * 8,
              (part ? Wl : Wh) + (size_t)(n0 + n) * DD + k0 + u * 8);
    }
}

__device__ __forceinline__ void s3_prefetchW(int l, __nv_bfloat16* sm)
{
    const int b = blockIdx.x;
    const int ph = b >> 7, nt = (b & 127) >> 2, kc = b & 3;
    s3_fillW(0, sm, kc * 256, nt * 128, g_wh[l][ph], g_wl[l][ph]);
    cp_commit();
}

__device__ __forceinline__ void stage3_gemm(int l, __nv_bfloat16* sm)
{
    const int tid = threadIdx.x, b = blockIdx.x;
    const int ph = b >> 7;
    const int nt = (b & 127) >> 2;
    const int kc = b & 3;
    const int n0 = nt * 128;
    const int kb = kc * 256;

    const __nv_bfloat16* Ah = ph ? g_hph : g_xph;
    const __nv_bfloat16* Al = ph ? g_hpl : g_xpl;
    const __nv_bfloat16* Wh = g_wh[l][ph];
    const __nv_bfloat16* Wl = g_wl[l][ph];

    const int w = tid >> 5, lane = tid & 31;
    const int wm = w & 1, wn = w >> 1;
    const int g = lane >> 2, t4 = lane & 3;
    const int tA = lane >> 3;
    const int aoff = ((tA & 1) * 8 + (lane & 7)) * 40 + (tA >> 1) * 8;
    const int boff = ((lane >> 4) * 8 + (lane & 7)) * 40 + ((lane >> 3) & 1) * 8;
    const unsigned smemBase = (unsigned)__cvta_generic_to_shared(sm);

    float D[2][4][4];
    #pragma unroll
    for (int im = 0; im < 2; im++)
        #pragma unroll
        for (int q = 0; q < 4; q++)
            D[im][q][0] = D[im][q][1] = D[im][q][2] = D[im][q][3] = 0.f;

    // W chunk 0 was prefetched before the preceding barrier; fill A only.
    s3_fillA(0, sm, kb, Ah, Al);
    cp_commit();

    for (int s = 0; s < 8; s++) {
        if (s < 7) {
            __nv_bfloat16* nb = sm + ((s + 1) & 1) * 15360;
            s3_fillA(s + 1, nb, kb, Ah, Al);
            s3_fillW(s + 1, nb, kb, n0, Wh, Wl);
            cp_commit();
            cp_wait1();
        } else {
            cp_wait0();
        }
        __syncthreads();
        const unsigned bufBase = smemBase + (unsigned)((s & 1) * 15360 * 2);
        #pragma unroll
        for (int ks = 0; ks < 2; ks++) {
            const unsigned kadd = ks * 16;
            unsigned ah[2][4], al[2][4];
            #pragma unroll
            for (int im = 0; im < 2; im++) {
                unsigned base = bufBase + 2u * ((wm * 32 + im * 16) * 40 + kadd + aoff);
                ldsm4(ah[im], base);
                ldsm4(al[im], base + 2u * 2560);
            }
            unsigned bh[2][4], bl[2][4];
            #pragma unroll
            for (int in2 = 0; in2 < 2; in2++) {
                unsigned base = bufBase + 2u * (5120 + (wn * 32 + in2 * 16) * 40 + kadd + boff);
                ldsm4(bh[in2], base);
                ldsm4(bl[in2], base + 2u * 5120);
            }
            #pragma unroll
            for (int im = 0; im < 2; im++)
                #pragma unroll
                for (int in8 = 0; in8 < 4; in8++) {
                    int in2 = in8 >> 1, o = (in8 & 1) * 2;
                    mma_x3(D[im][in8], ah[im], al[im],
                           bh[in2][o], bh[in2][o + 1], bl[in2][o], bl[in2][o + 1]);
                }
        }
        __syncthreads();
    }

    float* dst = &s_pt[ph][kc][0][0];
    #pragma unroll
    for (int im = 0; im < 2; im++) {
        int m0 = wm * 32 + im * 16 + g;
        #pragma unroll
        for (int in8 = 0; in8 < 4; in8++) {
            int col = n0 + wn * 32 + in8 * 8 + 2 * t4;
            *(float2*)(dst + (size_t)m0 * NG4 + col) =
                make_float2(D[im][in8][0], D[im][in8][1]);
            *(float2*)(dst + (size_t)(m0 + 8) * NG4 + col) =
                make_float2(D[im][in8][2], D[im][in8][3]);
        }
    }
}

// ============================ stage 3b (coalesced remap) =====================
__device__ __forceinline__ void stage3b(
    int l, int p, int t, float* __restrict__ out)
{
    const int gidx = blockIdx.x * NTHR + threadIdx.x;
    const int m = gidx >> 10, col = gidx & 1023;   // warp = 32 consecutive cols

    float G[4];
    #pragma unroll
    for (int g = 0; g < 4; g++) {
        size_t cg = (size_t)m * NG4 + g * DD + col;
        float ig = __ldcg(&s_pt[0][0][0][cg]) + __ldcg(&s_pt[0][1][0][cg])
                 + __ldcg(&s_pt[0][2][0][cg]) + __ldcg(&s_pt[0][3][0][cg]);
        float hg = __ldcg(&s_pt[1][0][0][cg]) + __ldcg(&s_pt[1][1][0][cg])
                 + __ldcg(&s_pt[1][2][0][cg]) + __ldcg(&s_pt[1][3][0][cg]);
        G[g] = fmaf(ig, __ldcg(&s_p2[cg]), __ldcg(&s_b4[cg]))
             + hg * __ldcg(&s_p3[cg]);
    }
    float cO = __ldcg(&s_fc[l][m * DD + col]);
    float cN = sigf(G[1]) * cO + sigf(G[0]) * tanhf(G[2]);
    float h  = sigf(G[3]) * tanhf(cN);
    s_fc[l][m * DD + col] = cN;
    s_fh[p ^ 1][l][m * DD + col] = h;
    bsplit(h, &g_fhh[p ^ 1][l][m * DD + col], &g_fhl[p ^ 1][l][m * DD + col]);
    if (l == 1) out[((size_t)t * BB + m) * DD + col] = h;
}

// ---------------- persistent kernel ----------------------------------------
__global__ void __launch_bounds__(NTHR, 2) alstm_persistent(Params P)
{
    extern __shared__ __align__(16) float smf[];
    __nv_bfloat16* sm = (__nv_bfloat16*)smf;
    const int tid = threadIdx.x, b = blockIdx.x;
    const int gtid = b * NTHR + tid, gsz = NCTA * NTHR;

    unsigned gen;
    asm volatile("ld.acquire.gpu.global.u32 %0, [%1];" : "=r"(gen) : "l"(&g_gen2));

    {   // zero recurrent state each replay
        float* z2 = &s_ac[0][0];
        for (int i = gtid; i < NL * BB * AA; i += gsz) z2[i] = 0.f;
        float* z3 = &s_fh[0][0][0];
        for (int i = gtid; i < 2 * NL * BB * DD; i += gsz) z3[i] = 0.f;
        float* z4 = &s_fc[0][0];
        for (int i = gtid; i < NL * BB * DD; i += gsz) z4[i] = 0.f;
        __nv_bfloat16* z5 = &g_ahh[0][0][0];
        __nv_bfloat16* z6 = &g_ahl[0][0][0];
        for (int i = gtid; i < 2 * NL * BB * AA; i += gsz) { z5[i] = __nv_bfloat16(0.f); z6[i] = __nv_bfloat16(0.f); }
        __nv_bfloat16* z7 = &g_fhh[0][0][0];
        __nv_bfloat16* z8 = &g_fhl[0][0][0];
        for (int i = gtid; i < 2 * NL * BB * DD; i += gsz) { z7[i] = __nv_bfloat16(0.f); z8[i] = __nv_bfloat16(0.f); }
    }
    {   // split x (whole sequence)
        const float4* s4 = (const float4*)P.x;
        for (int i = gtid; i < TT * BB * DD / 4; i += gsz) {
            float4 v = s4[i];
            float f[4] = {v.x, v.y, v.z, v.w};
            #pragma unroll
            for (int q = 0; q < 4; q++)
                bsplit(f[q], &g_xh[4 * i + q], &g_xl[4 * i + q]);
        }
    }
    {   // split stage3 weights
        const float* Wsrc[4] = {P.fwih[0], P.fwhh[0], P.fwih[1], P.fwhh[1]};
        #pragma unroll
        for (int mtx = 0; mtx < 4; mtx++) {
            const float4* s4 = (const float4*)Wsrc[mtx];
            __nv_bfloat16* dh = &g_wh[mtx >> 1][mtx & 1][0];
            __nv_bfloat16* dl = &g_wl[mtx >> 1][mtx & 1][0];
            for (int i = gtid; i < NG4 * DD / 4; i += gsz) {
                float4 v = s4[i];
                float f[4] = {v.x, v.y, v.z, v.w};
                #pragma unroll
                for (int q = 0; q < 4; q++)
                    bsplit(f[q], &dh[4 * i + q], &dl[4 * i + q]);
            }
        }
    }
    {   // split pw
        #pragma unroll
        for (int l = 0; l < 2; l++) {
            const float4* s4 = (const float4*)P.pw[l];
            for (int i = gtid; i < 14336 * 128 / 4; i += gsz) {
                float4 v = s4[i];
                float f[4] = {v.x, v.y, v.z, v.w};
                #pragma unroll
                for (int q = 0; q < 4; q++)
                    bsplit(f[q], &g_pwh[l][4 * i + q], &g_pwl[l][4 * i + q]);
            }
        }
    }
    {   // build composite stage1 weights
        #pragma unroll
        for (int l = 0; l < 2; l++) {
            const float* wih = P.awih[l];
            const float* whh = P.awhh[l];
            for (int i = gtid; i < 512 * KT1; i += gsz) {
                int n = i / KT1, k = i - n * KT1;
                float v = (k < AIN) ? wih[(size_t)n * AIN + k]
                                    : whh[n * AA + (k - AIN)];
                bsplit(v, &g_w1h[l][i], &g_w1l[l][i]);
            }
        }
    }
    grid_sync(gen);

    s1_prefetchW(0, sm);   // W for the first stage1

    for (int t = 0; t < TT; t++) {
        const int p = t & 1;
        #pragma unroll
        for (int l = 0; l < NL; l++) {
            const __nv_bfloat16* xh = (l == 0) ? g_xh + (size_t)t * BB * DD
                                               : g_fhh[p ^ 1][0];
            const __nv_bfloat16* xl = (l == 0) ? g_xl + (size_t)t * BB * DD
                                               : g_fhl[p ^ 1][0];
            stage1_gemm(l, p, sm, xh, xl);
            s2_prefetchW(l, sm);                 // hides behind barrier + s1_point
            grid_sync(gen);
            s1_point(l, p, P.abih[l], P.abhh[l]);
            grid_sync(gen);
            const float* xc = (l == 0) ? P.x + (size_t)t * BB * DD
                                       : s_fh[p ^ 1][0];
            stage2(l, p, xc, P.pb[l], P.fb[l], sm);
            s3_prefetchW(l, sm);                 // hides behind barrier
            grid_sync(gen);
            stage3_gemm(l, sm);
            grid_sync(gen);
            s1_prefetchW(l ^ 1, sm);             // W for next stage1
            stage3b(l, p, t, P.out);
            grid_sync(gen);
        }
    }
    cp_wait0();   // drain the last (unused) prefetch before exit
}

// ---------------- host launch ----------------------------------------------
extern "C" void kernel_launch(void* const* d_in, const int* in_sizes, int n_in,
                              void* d_out, int out_size)
{
    Params P;
    P.x       = (const float*)d_in[0];
    P.awih[0] = (const float*)d_in[1];  P.awih[1] = (const float*)d_in[10];
    P.awhh[0] = (const float*)d_in[2];  P.awhh[1] = (const float*)d_in[11];
    P.abih[0] = (const float*)d_in[3];  P.abih[1] = (const float*)d_in[12];
    P.abhh[0] = (const float*)d_in[4];  P.abhh[1] = (const float*)d_in[13];
    P.pw[0]   = (const float*)d_in[5];  P.pw[1]   = (const float*)d_in[14];
    P.pb[0]   = (const float*)d_in[6];  P.pb[1]   = (const float*)d_in[15];
    P.fwih[0] = (const float*)d_in[7];  P.fwih[1] = (const float*)d_in[16];
    P.fwhh[0] = (const float*)d_in[8];  P.fwhh[1] = (const float*)d_in[17];
    P.fb[0]   = (const float*)d_in[9];  P.fb[1]   = (const float*)d_in[18];
    P.out     = (float*)d_out;

    cudaFuncSetAttribute(alstm_persistent,
                         cudaFuncAttributeMaxDynamicSharedMemorySize,
                         SMEM_BYTES);
    alstm_persistent<<<NCTA, NTHR, SMEM_BYTES>>>(P);
}